// round 14
// baseline (speedup 1.0000x reference)
#include <cuda_runtime.h>
#include <cuda_fp16.h>
#include <stdint.h>
#include <math.h>

#define Bsz 512
#define Tsz 128
#define Hsz 512
#define Vsz 512
#define NBT 65536
#define G4  2048
#define TOKP 640

// ---------------- device scratch ----------------
__device__ __align__(128) __half g_seq0[(size_t)NBT*Hsz];     // layer-0 h-seq [b][t][u]
__device__ __align__(128) __half g_seq1[(size_t)NBT*Hsz];     // layer-1 h-seq [b][t][u]
__device__ __align__(128) __half g_h0[Bsz*Hsz], g_h1[Bsz*Hsz];
__device__ __align__(128) __half g_Wih[2*(size_t)G4*Hsz];
__device__ __align__(128) __half g_Whh[2*(size_t)G4*Hsz];
__device__ __align__(128) __half g_dW[(size_t)Vsz*Hsz];
__device__ __align__(128) __half g_embp[TOKP*Hsz];
__device__ __align__(128) __half g_Ep[(size_t)TOKP*Hsz*4];    // E' [tok][u][g]
__device__ __align__(128) float  g_wyv[G4], g_cbv[G4];        // layer-0 rank-1 terms
__device__ __align__(128) float  g_cbv1[G4];                  // layer-1 bias [u*4+g]
__device__ unsigned g_flag[4][8];

// ---------------- helpers ----------------
__device__ __forceinline__ uint32_t smem_u32(const void* p){
    uint32_t a; asm("{ .reg .u64 t; cvta.to.shared.u64 t, %1; cvt.u32.u64 %0, t; }" : "=r"(a) : "l"(p)); return a;
}
#define CP16(dst, src) asm volatile("cp.async.cg.shared.global [%0], [%1], 16;" :: "r"(dst), "l"(src))
#define CPCOMMIT()     asm volatile("cp.async.commit_group;" ::: "memory")
#define CPWAIT(n)      asm volatile("cp.async.wait_group %0;" :: "n"(n) : "memory")
#define LDSM4(r, a) asm volatile("ldmatrix.sync.aligned.m8n8.x4.shared.b16 {%0,%1,%2,%3}, [%4];" \
    : "=r"((r)[0]),"=r"((r)[1]),"=r"((r)[2]),"=r"((r)[3]) : "r"(a))

__device__ __forceinline__ void mma16816(float* d, const uint32_t* a, const uint32_t* b){
    asm volatile("mma.sync.aligned.m16n8k16.row.col.f32.f16.f16.f32 "
        "{%0,%1,%2,%3}, {%4,%5,%6,%7}, {%8,%9}, {%0,%1,%2,%3};"
        : "+f"(d[0]), "+f"(d[1]), "+f"(d[2]), "+f"(d[3])
        : "r"(a[0]), "r"(a[1]), "r"(a[2]), "r"(a[3]), "r"(b[0]), "r"(b[1]));
}
__device__ __forceinline__ float fast_ex2(float x){ float r; asm("ex2.approx.f32 %0, %1;" : "=f"(r) : "f"(x)); return r; }
__device__ __forceinline__ float fast_rcp(float x){ float r; asm("rcp.approx.f32 %0, %1;" : "=f"(r) : "f"(x)); return r; }
__device__ __forceinline__ float fsig(float x){ return fast_rcp(1.f + fast_ex2(-1.4426950408889634f*x)); }
__device__ __forceinline__ float ftanh(float x){ return 2.f*fast_rcp(1.f + fast_ex2(-2.885390081777927f*x)) - 1.f; }

// ============ generic FF GEMM (fp16 operands, fp32 accum) ============
#define CHW 4608
#define STW 9216
#define SMEMB 110592   // 3 stages

__device__ __forceinline__ void load_chunk(uint32_t sbase,
    const __half* __restrict__ A, const __half* __restrict__ B,
    int m0, int n0, int ck, int bmap, int amap, int tid)
{
    #pragma unroll
    for (int i = tid; i < 1024; i += 256) {
        int r = i >> 3, q = i & 7;
        int arow = amap ? (((r >> 5) << 9) + m0 + (r & 31)) : (m0 + r);
        CP16(sbase + (r*36 + q*4)*4, A + (size_t)arow*Hsz + ck*64 + q*8);
    }
    #pragma unroll
    for (int i = tid; i < 1024; i += 256) {
        int r = i >> 3, q = i & 7;
        int brow;
        if (bmap == 0)      brow = n0 + r;
        else                { int c = n0 + r; brow = (c & 511)*Tsz + (c >> 9); }
        CP16(sbase + (CHW + r*36 + q*4)*4, B + (size_t)brow*Hsz + ck*64 + q*8);
    }
    CPCOMMIT();
}

__device__ __forceinline__ void compute_chunk(uint32_t stg,
    float acc[4][4][4], int lane, int wm, int wn)
{
    int laneA_r = lane & 15;
    int laneA_c = (lane >> 4) * 4;
    int laneB_r = (lane & 7) + ((lane >> 4) << 3);
    int laneB_c = ((lane >> 3) & 1) * 4;
    #pragma unroll
    for (int ks = 0; ks < 4; ks++) {
        int kw = ks*8;
        uint32_t ah[4][4], bh[2][4];
        #pragma unroll
        for (int mt = 0; mt < 4; mt++) {
            uint32_t aw = (uint32_t)(wm*64 + mt*16 + laneA_r)*36 + kw + laneA_c;
            LDSM4(ah[mt], stg + aw*4);
        }
        #pragma unroll
        for (int np = 0; np < 2; np++) {
            uint32_t bw = (uint32_t)(wn*32 + np*16 + laneB_r)*36 + kw + laneB_c;
            LDSM4(bh[np], stg + (CHW + bw)*4);
        }
        #pragma unroll
        for (int mt = 0; mt < 4; mt++)
        #pragma unroll
        for (int nt = 0; nt < 4; nt++)
            mma16816(acc[mt][nt], ah[mt], &bh[nt>>1][(nt&1)*2]);
    }
}

// cmode: 0 fp32 row-major out; 2 E' [tok][u][g]
__global__ void __launch_bounds__(256,2)
gemm_mma(const __half* __restrict__ A, const __half* __restrict__ B,
         const float* __restrict__ br1, const float* __restrict__ br2,
         const float* __restrict__ bcn, void* __restrict__ Cv,
         int Ntot, int bmap, int mx, int cmode)
{
    extern __shared__ uint32_t sm[];
    uint32_t sbase = smem_u32(sm);
    int tid = threadIdx.x, lane = tid & 31, wid = tid >> 5;
    int wm = wid >> 2, wn = wid & 3;
    int bm = mx ? blockIdx.x : blockIdx.y;
    int bn = mx ? blockIdx.y : blockIdx.x;
    int m0 = cmode ? bm*32 : bm*128;
    int n0 = bn*128;
    int amap = (cmode != 0);

    float acc[4][4][4];
    #pragma unroll
    for (int a = 0; a < 4; a++)
    #pragma unroll
    for (int b = 0; b < 4; b++)
    #pragma unroll
    for (int cc = 0; cc < 4; cc++) acc[a][b][cc] = 0.f;

    load_chunk(sbase, A, B, m0, n0, 0, bmap, amap, tid);
    int st = 0, nst = 1;
    for (int k = 0; k < 8; k++) {
        if (k < 7) {
            load_chunk(sbase + nst*STW*4, A, B, m0, n0, k+1, bmap, amap, tid);
            CPWAIT(1);
        } else {
            CPWAIT(0);
        }
        __syncthreads();
        compute_chunk(sbase + st*STW*4, acc, lane, wm, wn);
        st = nst; nst = (nst + 1 == 3) ? 0 : nst + 1;
    }

    if (cmode) {
        __syncthreads();
        __half* sx = (__half*)sm;
        #pragma unroll
        for (int mt = 0; mt < 4; mt++) {
            #pragma unroll
            for (int half = 0; half < 2; half++) {
                int rloc = wm*64 + mt*16 + (lane >> 2) + half*8;
                int g = rloc >> 5, ul = rloc & 31;
                #pragma unroll
                for (int nt = 0; nt < 4; nt++) {
                    int cloc = wn*32 + nt*8 + (lane & 3)*2;
                    sx[(ul*132 + cloc)*4 + g]     = __float2half_rn(acc[mt][nt][half*2+0]);
                    sx[(ul*132 + cloc + 1)*4 + g] = __float2half_rn(acc[mt][nt][half*2+1]);
                }
            }
        }
        __syncthreads();
        #pragma unroll
        for (int i = tid; i < 4096; i += 256) {
            int tkl = i >> 5, ul = i & 31;
            uint2 v = *(uint2*)&sx[(ul*132 + tkl)*4];
            *(uint2*)((__half*)Cv + (((size_t)(n0 + tkl))*512 + m0 + ul)*4) = v;
        }
        return;
    }

    #pragma unroll
    for (int mt = 0; mt < 4; mt++) {
        #pragma unroll
        for (int half = 0; half < 2; half++) {
            int m = m0 + wm*64 + mt*16 + (lane >> 2) + half*8;
            float rb = br1 ? (br1[m] + br2[m]) : 0.f;
            #pragma unroll
            for (int nt = 0; nt < 4; nt++) {
                int c = n0 + wn*32 + nt*8 + (lane & 3)*2;
                float v0 = acc[mt][nt][half*2+0] + rb;
                float v1 = acc[mt][nt][half*2+1] + rb;
                if (bcn) { v0 += bcn[c]; v1 += bcn[c+1]; }
                *(float2*)((float*)Cv + (size_t)m*Ntot + c) = make_float2(v0, v1);
            }
        }
    }
}

// ============ persistent LSTM recurrence ============
// mode 0: gates = E'[tok] + y-term + Whh0·h(t-1)          (8 W chunks)
// mode 1: gates = Wih1·seqIn(t) + Whh1·h(t-1) + bias      (16 W chunks, fused input GEMM)
// SMEM: W 16ck x 64r x 36w = 147456B; H 3st x 128r x 36w = 55296B -> 202752B
#define PS_SMEM 202752
__device__ __forceinline__ int WOFFf(int ck,int r){ return (ck*64 + r)*36; }
__device__ __forceinline__ int HOFFf(int st,int r){ return 36864 + (st*128 + r)*36; }

__global__ void reset_flags(){ int i = threadIdx.x; if (i < 32) ((unsigned*)g_flag)[i] = 0u; }

__global__ void __launch_bounds__(256,1)
lstm_persist(int mode,
             const __half* __restrict__ seqIn,   // mode 1: layer-0 h-seq [b][t][u]
             const __half* __restrict__ Ep,
             const float* __restrict__ wyv, const float* __restrict__ cbv,
             const int* __restrict__ xtok, const float* __restrict__ yv,
             const __half* __restrict__ Wi,      // mode 1: Wih1
             const __half* __restrict__ Wh,      // Whh (layer 0 or 1)
             __half* __restrict__ h0, __half* __restrict__ h1,
             __half* __restrict__ seq)
{
    extern __shared__ uint32_t sm[];
    uint32_t sb = smem_u32(sm);
    int tid = threadIdx.x, lane = tid & 31, w = tid >> 5;
    int laneR = lane >> 2, laneC = lane & 3;
    int u0 = blockIdx.x * 16;
    int b0 = blockIdx.y * 128;
    int gid = blockIdx.y;
    int myck = u0 >> 6;

    int laneA_r = lane & 15;
    int laneA_c = (lane >> 4) * 4;
    int laneB_r = (lane & 7) + ((lane >> 4) << 3);
    int laneB_c = ((lane >> 3) & 1) * 4;

    // ---- persistent W tiles ----
    int nwck = (mode == 0) ? 8 : 16;
    for (int i = tid; i < nwck*512; i += 256) {
        int ck = i >> 9, rem = i & 511;
        int r = rem >> 3, q = rem & 7;
        int g = r >> 4, ul = r & 15;
        size_t row = (size_t)(g*Hsz + u0 + ul)*Hsz;
        const __half* src;
        if (mode == 0)      src = Wh + row + ck*64 + q*8;
        else if (ck < 8)    src = Wi + row + ck*64 + q*8;
        else                src = Wh + row + (ck-8)*64 + q*8;
        CP16(sb + (WOFFf(ck,r) + q*4)*4, src);
    }
    CPCOMMIT(); CPWAIT(0);
    __syncthreads();

    // ---- per-thread constant bias / y term ----
    float ybase[2][16];
    #pragma unroll
    for (int half = 0; half < 2; half++) {
        int b = b0 + w*16 + laneR + half*8;
        float yy = (mode == 0) ? yv[b] : 0.f;
        #pragma unroll
        for (int uh = 0; uh < 2; uh++)
        #pragma unroll
        for (int du = 0; du < 2; du++) {
            int u = u0 + laneC*2 + uh*8 + du;
            float4 cv = *(const float4*)(cbv + u*4);
            if (mode == 0) {
                float4 wv = *(const float4*)(wyv + u*4);
                ybase[half][uh*8+du*4+0] = yy*wv.x + cv.x;
                ybase[half][uh*8+du*4+1] = yy*wv.y + cv.y;
                ybase[half][uh*8+du*4+2] = yy*wv.z + cv.z;
                ybase[half][uh*8+du*4+3] = yy*wv.w + cv.w;
            } else {
                ybase[half][uh*8+du*4+0] = cv.x;
                ybase[half][uh*8+du*4+1] = cv.y;
                ybase[half][uh*8+du*4+2] = cv.z;
                ybase[half][uh*8+du*4+3] = cv.w;
            }
        }
    }

    __half* hb[2] = {h0, h1};
    float creg[2][2][2];
    #pragma unroll
    for (int a = 0; a < 2; a++)
    #pragma unroll
    for (int b = 0; b < 2; b++) { creg[a][b][0] = 0.f; creg[a][b][1] = 0.f; }

    for (int t = 0; t < Tsz; t++) {
        const __half* Hc = hb[t & 1];
        __half* Nx = hb[(t+1) & 1];
        unsigned tgt = 4u * (unsigned)t;

        // mode 0: gate inputs via E' gather
        float xv[2][16];
        if (mode == 0) {
            #pragma unroll
            for (int half = 0; half < 2; half++) {
                int b = b0 + w*16 + laneR + half*8;
                int tok = (t == 0) ? Vsz : xtok[b*Tsz + t - 1];
                #pragma unroll
                for (int uh = 0; uh < 2; uh++) {
                    int u = u0 + laneC*2 + uh*8;
                    uint4 v = *(const uint4*)(Ep + ((size_t)tok*Hsz + u)*4);
                    __half2 p0 = *(__half2*)&v.x, p1 = *(__half2*)&v.y;
                    __half2 p2 = *(__half2*)&v.z, p3 = *(__half2*)&v.w;
                    xv[half][uh*8+0] = __half2float(p0.x) + ybase[half][uh*8+0];
                    xv[half][uh*8+1] = __half2float(p0.y) + ybase[half][uh*8+1];
                    xv[half][uh*8+2] = __half2float(p1.x) + ybase[half][uh*8+2];
                    xv[half][uh*8+3] = __half2float(p1.y) + ybase[half][uh*8+3];
                    xv[half][uh*8+4] = __half2float(p2.x) + ybase[half][uh*8+4];
                    xv[half][uh*8+5] = __half2float(p2.y) + ybase[half][uh*8+5];
                    xv[half][uh*8+6] = __half2float(p3.x) + ybase[half][uh*8+6];
                    xv[half][uh*8+7] = __half2float(p3.y) + ybase[half][uh*8+7];
                }
            }
        }

        float acc[8][4];
        #pragma unroll
        for (int i = 0; i < 8; i++)
        #pragma unroll
        for (int j = 0; j < 4; j++) acc[i][j] = 0.f;

        auto wait_ck = [&](int fck){
            unsigned v;
            do { asm volatile("ld.acquire.gpu.global.u32 %0, [%1];"
                              : "=r"(v) : "l"(&g_flag[gid][fck])); } while (v < tgt);
        };

        // chunk plan: mode 0 -> recurrent chunks at W[0..7];
        //             mode 1 -> input chunks W[0..7] (no wait), recurrent W[8..15]
        int cklo, nck;
        if (mode == 0) { cklo = 0; nck = (t > 0) ? 8 : 0; }
        else           { cklo = 0; nck = (t > 0) ? 16 : 8; }

        if (nck > 0) {
            auto ldc = [&](int ck, int st){
                #pragma unroll
                for (int i = tid; i < 1024; i += 256) {
                    int r = i >> 3, q = i & 7;
                    const __half* src;
                    if (mode == 1 && ck < 8)
                        src = seqIn + ((size_t)(b0 + r)*Tsz + t)*Hsz + ck*64 + q*8;
                    else {
                        int rck = (mode == 1) ? ck - 8 : ck;
                        src = Hc + (size_t)(b0 + r)*Hsz + rck*64 + q*8;
                    }
                    CP16(sb + (HOFFf(st,r) + q*4)*4, src);
                }
                CPCOMMIT();
            };
            auto needw = [&](int ck){ return (mode == 0) || (ck >= 8); };
            auto fidx  = [&](int ck){ return (mode == 0) ? ck : ck - 8; };

            if (needw(cklo)) wait_ck(fidx(cklo));
            ldc(cklo, 0);
            int st = 0, nst = 1;
            for (int ck = cklo; ck < nck; ck++) {
                if (ck + 1 < nck) {
                    if (needw(ck+1)) wait_ck(fidx(ck+1));
                    ldc(ck+1, nst); CPWAIT(1);
                } else CPWAIT(0);
                __syncthreads();
                #pragma unroll
                for (int ks = 0; ks < 4; ks++) {
                    int kw = ks*8;
                    uint32_t ah[4], bh[4][4];
                    uint32_t aw = (uint32_t)(HOFFf(st, w*16 + laneA_r)) + kw + laneA_c;
                    LDSM4(ah, sb + aw*4);
                    #pragma unroll
                    for (int np = 0; np < 4; np++) {
                        uint32_t bw = (uint32_t)(WOFFf(ck, np*16 + laneB_r)) + kw + laneB_c;
                        LDSM4(bh[np], sb + bw*4);
                    }
                    #pragma unroll
                    for (int nt = 0; nt < 8; nt++)
                        mma16816(acc[nt], ah, &bh[nt>>1][(nt&1)*2]);
                }
                st = nst; nst = (nst + 1 == 3) ? 0 : nst + 1;
            }
        }

        // epilogue
        #pragma unroll
        for (int half = 0; half < 2; half++) {
            int b = b0 + w*16 + laneR + half*8;
            #pragma unroll
            for (int uh = 0; uh < 2; uh++) {
                float hn[2];
                #pragma unroll
                for (int du = 0; du < 2; du++) {
                    int q = half*2 + du;
                    float base0, base1, base2, base3;
                    if (mode == 0) {
                        base0 = xv[half][uh*8+du*4+0]; base1 = xv[half][uh*8+du*4+1];
                        base2 = xv[half][uh*8+du*4+2]; base3 = xv[half][uh*8+du*4+3];
                    } else {
                        base0 = ybase[half][uh*8+du*4+0]; base1 = ybase[half][uh*8+du*4+1];
                        base2 = ybase[half][uh*8+du*4+2]; base3 = ybase[half][uh*8+du*4+3];
                    }
                    float gi = acc[0*2+uh][q] + base0;
                    float gf = acc[1*2+uh][q] + base1;
                    float gg = acc[2*2+uh][q] + base2;
                    float go = acc[3*2+uh][q] + base3;
                    float is = fsig(gi);
                    float fs = fsig(gf);
                    float os = fsig(go);
                    float gt = ftanh(gg);
                    float cn = fs*creg[half][uh][du] + is*gt;
                    creg[half][uh][du] = cn;
                    hn[du] = os*ftanh(cn);
                }
                int u2 = u0 + laneC*2 + uh*8;
                __half2 hp;
                hp.x = __float2half_rn(hn[0]);
                hp.y = __float2half_rn(hn[1]);
                *(__half2*)(Nx + (size_t)b*Hsz + u2) = hp;
                *(__half2*)(seq + ((size_t)b*Tsz + t)*Hsz + u2) = hp;
            }
        }

        if (t < Tsz - 1) {
            __threadfence();
            __syncthreads();
            if (tid == 0) atomicAdd(&g_flag[gid][myck], 1u);
        }
    }
}

// ---------------- small kernels ----------------
__global__ void conv_kernel(const float* __restrict__ s, __half* __restrict__ h, int n4){
    int i = blockIdx.x*blockDim.x + threadIdx.x;
    if (i < n4) {
        float4 v = ((const float4*)s)[i];
        __half2 a, b;
        a.x = __float2half_rn(v.x); a.y = __float2half_rn(v.y);
        b.x = __float2half_rn(v.z); b.y = __float2half_rn(v.w);
        ((__half2*)h)[i*2]   = a;
        ((__half2*)h)[i*2+1] = b;
    }
}
__global__ void prep_y(const float* __restrict__ Wih, const float* __restrict__ yW,
                       const float* __restrict__ yb, const float* __restrict__ bih,
                       const float* __restrict__ bhh,
                       float* __restrict__ wyv, float* __restrict__ cbv)
{
    int n = blockIdx.x*8 + (threadIdx.x >> 5);
    int lane = threadIdx.x & 31;
    const float* wr = Wih + (size_t)n*Hsz;
    float s1 = 0.f, s2 = 0.f;
    for (int k = lane; k < Hsz; k += 32) { float wv = wr[k]; s1 += wv*yW[k]; s2 += wv*yb[k]; }
    #pragma unroll
    for (int o = 16; o; o >>= 1) {
        s1 += __shfl_down_sync(0xFFFFFFFFu, s1, o);
        s2 += __shfl_down_sync(0xFFFFFFFFu, s2, o);
    }
    if (lane == 0) {
        int g = n >> 9, u = n & 511;
        wyv[u*4+g] = s1;
        cbv[u*4+g] = s2 + bih[n] + bhh[n];
    }
}
__global__ void prep_b1(const float* __restrict__ bih, const float* __restrict__ bhh,
                        float* __restrict__ cbv1)
{
    int n = blockIdx.x*256 + threadIdx.x;
    if (n < G4) {
        int g = n >> 9, u = n & 511;
        cbv1[u*4+g] = bih[n] + bhh[n];
    }
}

// ---------------- launch ----------------
extern "C" void kernel_launch(void* const* d_in, const int* in_sizes, int n_in,
                              void* d_out, int out_size)
{
    const int*   x    = (const int*)  d_in[0];
    const float* y    = (const float*)d_in[1];
    const float* emb  = (const float*)d_in[2];
    const float* yW   = (const float*)d_in[3];
    const float* yb   = (const float*)d_in[4];
    const float* Wih  = (const float*)d_in[5];
    const float* Whh  = (const float*)d_in[6];
    const float* bih  = (const float*)d_in[7];
    const float* bhh  = (const float*)d_in[8];
    const float* decW = (const float*)d_in[9];
    const float* decb = (const float*)d_in[10];
    float* out = (float*)d_out;

    __half *seq0, *seq1, *Wih_c, *Whh_c, *dW_c, *h0, *h1, *embp, *Ep;
    float *wyv, *cbv, *cbv1;
    cudaGetSymbolAddress((void**)&seq0,  g_seq0);
    cudaGetSymbolAddress((void**)&seq1,  g_seq1);
    cudaGetSymbolAddress((void**)&h0,    g_h0);
    cudaGetSymbolAddress((void**)&h1,    g_h1);
    cudaGetSymbolAddress((void**)&Wih_c, g_Wih);
    cudaGetSymbolAddress((void**)&Whh_c, g_Whh);
    cudaGetSymbolAddress((void**)&dW_c,  g_dW);
    cudaGetSymbolAddress((void**)&embp,  g_embp);
    cudaGetSymbolAddress((void**)&Ep,    g_Ep);
    cudaGetSymbolAddress((void**)&wyv,   g_wyv);
    cudaGetSymbolAddress((void**)&cbv,   g_cbv);
    cudaGetSymbolAddress((void**)&cbv1,  g_cbv1);

    cudaFuncSetAttribute(gemm_mma, cudaFuncAttributeMaxDynamicSharedMemorySize, SMEMB);
    cudaFuncSetAttribute(lstm_persist, cudaFuncAttributeMaxDynamicSharedMemorySize, PS_SMEM);

    const int nW4 = 2*G4*Hsz/4;
    conv_kernel<<<(nW4+255)/256, 256>>>(Wih, Wih_c, nW4);
    conv_kernel<<<(nW4+255)/256, 256>>>(Whh, Whh_c, nW4);
    conv_kernel<<<(Vsz*Hsz/4+255)/256, 256>>>(decW, dW_c, Vsz*Hsz/4);
    conv_kernel<<<(513*Hsz/4+255)/256, 256>>>(emb, embp, 513*Hsz/4);
    prep_y<<<G4/8, 256>>>(Wih, yW, yb, bih, bhh, wyv, cbv);
    prep_b1<<<G4/256, 256>>>(bih + G4, bhh + G4, cbv1);

    // E' = Wih0 · embp^T -> [tok][u][g]
    gemm_mma<<<dim3(16, TOKP/128), 256, SMEMB>>>(
        Wih_c, embp, nullptr, nullptr, nullptr, Ep, TOKP, 0, 1, 2);

    // ---- layer 0: recurrence with E' gather ----
    reset_flags<<<1, 32>>>();
    lstm_persist<<<dim3(Hsz/16, Bsz/128), 256, PS_SMEM>>>(
        0, nullptr, Ep, wyv, cbv, x, y, nullptr, Whh_c, h0, h1, seq0);

    // ---- layer 1: fused input-GEMM + recurrence ----
    reset_flags<<<1, 32>>>();
    lstm_persist<<<dim3(Hsz/16, Bsz/128), 256, PS_SMEM>>>(
        1, seq0, Ep, wyv, cbv1, x, y,
        Wih_c + (size_t)G4*Hsz, Whh_c + (size_t)G4*Hsz, h0, h1, seq1);

    // ---- decoder ----
    gemm_mma<<<dim3(Vsz/128, NBT/128), 256, SMEMB>>>(
        seq1, dW_c, nullptr, nullptr, decb, out, Vsz, 0, 0, 0);
}

// round 15
// speedup vs baseline: 1.1074x; 1.1074x over previous
#include <cuda_runtime.h>
#include <cuda_fp16.h>
#include <stdint.h>
#include <math.h>

#define Bsz 512
#define Tsz 128
#define Hsz 512
#define Vsz 512
#define NBT 65536
#define G4  2048
#define TOKP 640

// ---------------- device scratch ----------------
__device__ __align__(128) __half g_seq[(size_t)NBT*Hsz];      // L0: [t][b][u]; L1: [b][t][u]
__device__ __align__(128) __half g_xgT[(size_t)Tsz*G4*Bsz];   // [t][u][b][g] fp16
__device__ __align__(128) __half g_h0[Bsz*Hsz], g_h1[Bsz*Hsz];
__device__ __align__(128) __half g_Wih[2*(size_t)G4*Hsz];
__device__ __align__(128) __half g_Whh[2*(size_t)G4*Hsz];
__device__ __align__(128) __half g_dW[(size_t)Vsz*Hsz];
__device__ __align__(128) __half g_embp[TOKP*Hsz];
__device__ __align__(128) __half g_Ep[(size_t)TOKP*Hsz*4];    // E' [tok][u][g]
__device__ __align__(128) float  g_wyv[G4], g_cbv[G4];
__device__ unsigned g_flag[4][8];

// ---------------- helpers ----------------
__device__ __forceinline__ uint32_t smem_u32(const void* p){
    uint32_t a; asm("{ .reg .u64 t; cvta.to.shared.u64 t, %1; cvt.u32.u64 %0, t; }" : "=r"(a) : "l"(p)); return a;
}
#define CP16(dst, src) asm volatile("cp.async.cg.shared.global [%0], [%1], 16;" :: "r"(dst), "l"(src))
#define CPCOMMIT()     asm volatile("cp.async.commit_group;" ::: "memory")
#define CPWAIT(n)      asm volatile("cp.async.wait_group %0;" :: "n"(n) : "memory")
#define LDSM4(r, a) asm volatile("ldmatrix.sync.aligned.m8n8.x4.shared.b16 {%0,%1,%2,%3}, [%4];" \
    : "=r"((r)[0]),"=r"((r)[1]),"=r"((r)[2]),"=r"((r)[3]) : "r"(a))

__device__ __forceinline__ void mma16816(float* d, const uint32_t* a, const uint32_t* b){
    asm volatile("mma.sync.aligned.m16n8k16.row.col.f32.f16.f16.f32 "
        "{%0,%1,%2,%3}, {%4,%5,%6,%7}, {%8,%9}, {%0,%1,%2,%3};"
        : "+f"(d[0]), "+f"(d[1]), "+f"(d[2]), "+f"(d[3])
        : "r"(a[0]), "r"(a[1]), "r"(a[2]), "r"(a[3]), "r"(b[0]), "r"(b[1]));
}
__device__ __forceinline__ float fast_ex2(float x){ float r; asm("ex2.approx.f32 %0, %1;" : "=f"(r) : "f"(x)); return r; }
__device__ __forceinline__ float fast_rcp(float x){ float r; asm("rcp.approx.f32 %0, %1;" : "=f"(r) : "f"(x)); return r; }
__device__ __forceinline__ float fsig(float x){ return fast_rcp(1.f + fast_ex2(-1.4426950408889634f*x)); }
__device__ __forceinline__ float ftanh(float x){ return 2.f*fast_rcp(1.f + fast_ex2(-2.885390081777927f*x)) - 1.f; }

// ============ generic FF GEMM (fp16 operands, fp32 accum) ============
#define CHW 4608
#define STW 9216
#define SMEMB 110592   // 3 stages

__device__ __forceinline__ void load_chunk(uint32_t sbase,
    const __half* __restrict__ A, const __half* __restrict__ B,
    int m0, int n0, int ck, int amap, int tid)
{
    #pragma unroll
    for (int i = tid; i < 1024; i += 256) {
        int r = i >> 3, q = i & 7;
        int arow = amap ? (((r >> 5) << 9) + m0 + (r & 31)) : (m0 + r);
        CP16(sbase + (r*36 + q*4)*4, A + (size_t)arow*Hsz + ck*64 + q*8);
    }
    #pragma unroll
    for (int i = tid; i < 1024; i += 256) {
        int r = i >> 3, q = i & 7;
        CP16(sbase + (CHW + r*36 + q*4)*4, B + (size_t)(n0 + r)*Hsz + ck*64 + q*8);
    }
    CPCOMMIT();
}

__device__ __forceinline__ void compute_chunk(uint32_t stg,
    float acc[4][4][4], int lane, int wm, int wn)
{
    int laneA_r = lane & 15;
    int laneA_c = (lane >> 4) * 4;
    int laneB_r = (lane & 7) + ((lane >> 4) << 3);
    int laneB_c = ((lane >> 3) & 1) * 4;
    #pragma unroll
    for (int ks = 0; ks < 4; ks++) {
        int kw = ks*8;
        uint32_t ah[4][4], bh[2][4];
        #pragma unroll
        for (int mt = 0; mt < 4; mt++) {
            uint32_t aw = (uint32_t)(wm*64 + mt*16 + laneA_r)*36 + kw + laneA_c;
            LDSM4(ah[mt], stg + aw*4);
        }
        #pragma unroll
        for (int np = 0; np < 2; np++) {
            uint32_t bw = (uint32_t)(wn*32 + np*16 + laneB_r)*36 + kw + laneB_c;
            LDSM4(bh[np], stg + (CHW + bw)*4);
        }
        #pragma unroll
        for (int mt = 0; mt < 4; mt++)
        #pragma unroll
        for (int nt = 0; nt < 4; nt++)
            mma16816(acc[mt][nt], ah[mt], &bh[nt>>1][(nt&1)*2]);
    }
}

// cmode: 0 fp32 row-major out; 1 xgT [t][u][b][g]; 2 E' [tok][u][g]
__global__ void __launch_bounds__(256,2)
gemm_mma(const __half* __restrict__ A, const __half* __restrict__ B,
         const float* __restrict__ br1, const float* __restrict__ br2,
         const float* __restrict__ bcn, void* __restrict__ Cv,
         int Ntot, int mx, int cmode)
{
    extern __shared__ uint32_t sm[];
    uint32_t sbase = smem_u32(sm);
    int tid = threadIdx.x, lane = tid & 31, wid = tid >> 5;
    int wm = wid >> 2, wn = wid & 3;
    int bm = mx ? blockIdx.x : blockIdx.y;
    int bn = mx ? blockIdx.y : blockIdx.x;
    int m0 = cmode ? bm*32 : bm*128;
    int n0 = bn*128;
    int amap = (cmode != 0);

    float acc[4][4][4];
    #pragma unroll
    for (int a = 0; a < 4; a++)
    #pragma unroll
    for (int b = 0; b < 4; b++)
    #pragma unroll
    for (int cc = 0; cc < 4; cc++) acc[a][b][cc] = 0.f;

    load_chunk(sbase, A, B, m0, n0, 0, amap, tid);
    int st = 0, nst = 1;
    for (int k = 0; k < 8; k++) {
        if (k < 7) {
            load_chunk(sbase + nst*STW*4, A, B, m0, n0, k+1, amap, tid);
            CPWAIT(1);
        } else {
            CPWAIT(0);
        }
        __syncthreads();
        compute_chunk(sbase + st*STW*4, acc, lane, wm, wn);
        st = nst; nst = (nst + 1 == 3) ? 0 : nst + 1;
    }

    if (cmode) {
        // ---- transpose epilogue: SMEM [ul(32)][cloc(128,pad132)][g(4)] halves ----
        __syncthreads();
        __half* sx = (__half*)sm;
        #pragma unroll
        for (int mt = 0; mt < 4; mt++) {
            #pragma unroll
            for (int half = 0; half < 2; half++) {
                int rloc = wm*64 + mt*16 + (lane >> 2) + half*8;
                int g = rloc >> 5, ul = rloc & 31;
                int nrow = (g << 9) + m0 + ul;
                float rb = br1 ? (br1[nrow] + br2[nrow]) : 0.f;
                #pragma unroll
                for (int nt = 0; nt < 4; nt++) {
                    int cloc = wn*32 + nt*8 + (lane & 3)*2;
                    sx[(ul*132 + cloc)*4 + g]     = __float2half_rn(acc[mt][nt][half*2+0] + rb);
                    sx[(ul*132 + cloc + 1)*4 + g] = __float2half_rn(acc[mt][nt][half*2+1] + rb);
                }
            }
        }
        __syncthreads();
        if (cmode == 1) {
            // B rows were t-major bt = n0 + bl -> t = (n0>>9), b = (n0&511)+bl
            int t = n0 >> 9, bwin = n0 & 511;
            #pragma unroll
            for (int i = tid; i < 4096; i += 256) {
                int ul = i >> 7, bl = i & 127;
                uint2 v = *(uint2*)&sx[(ul*132 + bl)*4];
                *(uint2*)((__half*)Cv + (((size_t)t*512 + m0 + ul)*512 + bwin + bl)*4) = v;
            }
        } else {
            #pragma unroll
            for (int i = tid; i < 4096; i += 256) {
                int tkl = i >> 5, ul = i & 31;
                uint2 v = *(uint2*)&sx[(ul*132 + tkl)*4];
                *(uint2*)((__half*)Cv + (((size_t)(n0 + tkl))*512 + m0 + ul)*4) = v;
            }
        }
        return;
    }

    #pragma unroll
    for (int mt = 0; mt < 4; mt++) {
        #pragma unroll
        for (int half = 0; half < 2; half++) {
            int m = m0 + wm*64 + mt*16 + (lane >> 2) + half*8;
            float rb = br1 ? (br1[m] + br2[m]) : 0.f;
            #pragma unroll
            for (int nt = 0; nt < 4; nt++) {
                int c = n0 + wn*32 + nt*8 + (lane & 3)*2;
                float v0 = acc[mt][nt][half*2+0] + rb;
                float v1 = acc[mt][nt][half*2+1] + rb;
                if (bcn) { v0 += bcn[c]; v1 += bcn[c+1]; }
                *(float2*)((float*)Cv + (size_t)m*Ntot + c) = make_float2(v0, v1);
            }
        }
    }
}

// ============ persistent LSTM recurrence ============
#define PS_SMEM 129536
__device__ __forceinline__ int WOFFf(int ck,int r){ return (ck*64 + r)*36; }
__device__ __forceinline__ int HOFFf(int st,int r){ return 18432 + (st*128 + r)*36; }

__global__ void reset_flags(){ int i = threadIdx.x; if (i < 32) ((unsigned*)g_flag)[i] = 0u; }

// mode 0: layer 0 — gates from E' gather + rank-1 y term; seq written T-MAJOR [t][b][u]
// mode 1: layer 1 — gates from xgT [t][u][b][g]; seq written B-MAJOR [b][t][u]
__global__ void __launch_bounds__(256,1)
lstm_persist(int mode, const __half* __restrict__ xg,
             const __half* __restrict__ Ep,
             const float* __restrict__ wyv, const float* __restrict__ cbv,
             const int* __restrict__ xtok, const float* __restrict__ yv,
             const __half* __restrict__ W,
             __half* __restrict__ h0, __half* __restrict__ h1,
             __half* __restrict__ seq)
{
    extern __shared__ uint32_t sm[];
    uint32_t sb = smem_u32(sm);
    int tid = threadIdx.x, lane = tid & 31, w = tid >> 5;
    int laneR = lane >> 2, laneC = lane & 3;
    int u0 = blockIdx.x * 16;
    int b0 = blockIdx.y * 128;
    int gid = blockIdx.y;
    int myck = u0 >> 6;

    int laneA_r = lane & 15;
    int laneA_c = (lane >> 4) * 4;
    int laneB_r = (lane & 7) + ((lane >> 4) << 3);
    int laneB_c = ((lane >> 3) & 1) * 4;

    // ---- persistent W tile ----
    for (int i = tid; i < 4096; i += 256) {
        int ck = i >> 9, rem = i & 511;
        int r = rem >> 3, q = rem & 7;
        int g = r >> 4, ul = r & 15;
        CP16(sb + (WOFFf(ck,r) + q*4)*4,
             W + ((size_t)(g*Hsz + u0 + ul))*Hsz + ck*64 + q*8);
    }
    CPCOMMIT(); CPWAIT(0);
    __syncthreads();

    // ---- mode 0: per-thread constant y-conditioning term ----
    float ybase[2][16];
    if (mode == 0) {
        #pragma unroll
        for (int half = 0; half < 2; half++) {
            int b = b0 + w*16 + laneR + half*8;
            float yy = yv[b];
            #pragma unroll
            for (int uh = 0; uh < 2; uh++)
            #pragma unroll
            for (int du = 0; du < 2; du++) {
                int u = u0 + laneC*2 + uh*8 + du;
                float4 wv = *(const float4*)(wyv + u*4);
                float4 cv = *(const float4*)(cbv + u*4);
                ybase[half][uh*8+du*4+0] = yy*wv.x + cv.x;
                ybase[half][uh*8+du*4+1] = yy*wv.y + cv.y;
                ybase[half][uh*8+du*4+2] = yy*wv.z + cv.z;
                ybase[half][uh*8+du*4+3] = yy*wv.w + cv.w;
            }
        }
    }

    __half* hb[2] = {h0, h1};
    float creg[2][2][2];
    #pragma unroll
    for (int a = 0; a < 2; a++)
    #pragma unroll
    for (int b = 0; b < 2; b++) { creg[a][b][0] = 0.f; creg[a][b][1] = 0.f; }

    for (int t = 0; t < Tsz; t++) {
        const __half* Hc = hb[t & 1];
        __half* Nx = hb[(t+1) & 1];
        unsigned tgt = 4u * (unsigned)t;

        float xv[2][16];
        if (mode == 0) {
            #pragma unroll
            for (int half = 0; half < 2; half++) {
                int b = b0 + w*16 + laneR + half*8;
                int tok = (t == 0) ? Vsz : xtok[b*Tsz + t - 1];
                #pragma unroll
                for (int uh = 0; uh < 2; uh++) {
                    int u = u0 + laneC*2 + uh*8;
                    uint4 v = *(const uint4*)(Ep + ((size_t)tok*Hsz + u)*4);
                    __half2 p0 = *(__half2*)&v.x, p1 = *(__half2*)&v.y;
                    __half2 p2 = *(__half2*)&v.z, p3 = *(__half2*)&v.w;
                    xv[half][uh*8+0] = __half2float(p0.x) + ybase[half][uh*8+0];
                    xv[half][uh*8+1] = __half2float(p0.y) + ybase[half][uh*8+1];
                    xv[half][uh*8+2] = __half2float(p1.x) + ybase[half][uh*8+2];
                    xv[half][uh*8+3] = __half2float(p1.y) + ybase[half][uh*8+3];
                    xv[half][uh*8+4] = __half2float(p2.x) + ybase[half][uh*8+4];
                    xv[half][uh*8+5] = __half2float(p2.y) + ybase[half][uh*8+5];
                    xv[half][uh*8+6] = __half2float(p3.x) + ybase[half][uh*8+6];
                    xv[half][uh*8+7] = __half2float(p3.y) + ybase[half][uh*8+7];
                }
            }
        } else {
            const __half* xgt = xg + (size_t)t*G4*Bsz;
            #pragma unroll
            for (int half = 0; half < 2; half++) {
                int b = b0 + w*16 + laneR + half*8;
                #pragma unroll
                for (int uh = 0; uh < 2; uh++)
                #pragma unroll
                for (int du = 0; du < 2; du++) {
                    int u = u0 + laneC*2 + uh*8 + du;
                    uint2 v = *(const uint2*)(xgt + ((size_t)u*512 + b)*4);
                    __half2 p0 = *(__half2*)&v.x;
                    __half2 p1 = *(__half2*)&v.y;
                    xv[half][uh*8+du*4+0] = __half2float(p0.x);
                    xv[half][uh*8+du*4+1] = __half2float(p0.y);
                    xv[half][uh*8+du*4+2] = __half2float(p1.x);
                    xv[half][uh*8+du*4+3] = __half2float(p1.y);
                }
            }
        }

        float acc[8][4];
        #pragma unroll
        for (int i = 0; i < 8; i++)
        #pragma unroll
        for (int j = 0; j < 4; j++) acc[i][j] = 0.f;

        if (t > 0) {
            auto wait_ck = [&](int ck){
                unsigned v;
                do { asm volatile("ld.acquire.gpu.global.u32 %0, [%1];"
                                  : "=r"(v) : "l"(&g_flag[gid][ck])); } while (v < tgt);
            };
            auto ldh = [&](int ck, int st){
                #pragma unroll
                for (int i = tid; i < 1024; i += 256) {
                    int r = i >> 3, q = i & 7;
                    CP16(sb + (HOFFf(st,r) + q*4)*4,
                         Hc + (size_t)(b0 + r)*Hsz + ck*64 + q*8);
                }
                CPCOMMIT();
            };

            wait_ck(0);
            ldh(0, 0);
            int st = 0, nst = 1;
            for (int ck = 0; ck < 8; ck++) {
                if (ck < 7) { wait_ck(ck+1); ldh(ck+1, nst); CPWAIT(1); }
                else        { CPWAIT(0); }
                __syncthreads();
                #pragma unroll
                for (int ks = 0; ks < 4; ks++) {
                    int kw = ks*8;
                    uint32_t ah[4], bh[4][4];
                    uint32_t aw = (uint32_t)(HOFFf(st, w*16 + laneA_r)) + kw + laneA_c;
                    LDSM4(ah, sb + aw*4);
                    #pragma unroll
                    for (int np = 0; np < 4; np++) {
                        uint32_t bw = (uint32_t)(WOFFf(ck, np*16 + laneB_r)) + kw + laneB_c;
                        LDSM4(bh[np], sb + bw*4);
                    }
                    #pragma unroll
                    for (int nt = 0; nt < 8; nt++)
                        mma16816(acc[nt], ah, &bh[nt>>1][(nt&1)*2]);
                }
                st = nst; nst = (nst + 1 == 3) ? 0 : nst + 1;
            }
        }

        // epilogue: gates + state update (c in registers, fast transcendentals)
        #pragma unroll
        for (int half = 0; half < 2; half++) {
            int b = b0 + w*16 + laneR + half*8;
            #pragma unroll
            for (int uh = 0; uh < 2; uh++) {
                float hn[2];
                #pragma unroll
                for (int du = 0; du < 2; du++) {
                    int q = half*2 + du;
                    float gi = acc[0*2+uh][q] + xv[half][uh*8+du*4+0];
                    float gf = acc[1*2+uh][q] + xv[half][uh*8+du*4+1];
                    float gg = acc[2*2+uh][q] + xv[half][uh*8+du*4+2];
                    float go = acc[3*2+uh][q] + xv[half][uh*8+du*4+3];
                    float is = fsig(gi);
                    float fs = fsig(gf);
                    float os = fsig(go);
                    float gt = ftanh(gg);
                    float cn = fs*creg[half][uh][du] + is*gt;
                    creg[half][uh][du] = cn;
                    hn[du] = os*ftanh(cn);
                }
                int u2 = u0 + laneC*2 + uh*8;
                __half2 hp;
                hp.x = __float2half_rn(hn[0]);
                hp.y = __float2half_rn(hn[1]);
                *(__half2*)(Nx + (size_t)b*Hsz + u2) = hp;
                size_t so = (mode == 0)
                    ? ((size_t)t*Bsz + b)*Hsz + u2     // t-major for xg GEMM
                    : ((size_t)b*Tsz + t)*Hsz + u2;    // b-major for decoder
                *(__half2*)(seq + so) = hp;
            }
        }

        if (t < Tsz - 1) {
            __threadfence();
            __syncthreads();
            if (tid == 0) atomicAdd(&g_flag[gid][myck], 1u);
        }
    }
}

// ---------------- small kernels ----------------
__global__ void conv_kernel(const float* __restrict__ s, __half* __restrict__ h, int n4){
    int i = blockIdx.x*blockDim.x + threadIdx.x;
    if (i < n4) {
        float4 v = ((const float4*)s)[i];
        __half2 a, b;
        a.x = __float2half_rn(v.x); a.y = __float2half_rn(v.y);
        b.x = __float2half_rn(v.z); b.y = __float2half_rn(v.w);
        ((__half2*)h)[i*2]   = a;
        ((__half2*)h)[i*2+1] = b;
    }
}
__global__ void prep_y(const float* __restrict__ Wih, const float* __restrict__ yW,
                       const float* __restrict__ yb, const float* __restrict__ bih,
                       const float* __restrict__ bhh,
                       float* __restrict__ wyv, float* __restrict__ cbv)
{
    int n = blockIdx.x*8 + (threadIdx.x >> 5);
    int lane = threadIdx.x & 31;
    const float* wr = Wih + (size_t)n*Hsz;
    float s1 = 0.f, s2 = 0.f;
    for (int k = lane; k < Hsz; k += 32) { float wv = wr[k]; s1 += wv*yW[k]; s2 += wv*yb[k]; }
    #pragma unroll
    for (int o = 16; o; o >>= 1) {
        s1 += __shfl_down_sync(0xFFFFFFFFu, s1, o);
        s2 += __shfl_down_sync(0xFFFFFFFFu, s2, o);
    }
    if (lane == 0) {
        int g = n >> 9, u = n & 511;
        wyv[u*4+g] = s1;
        cbv[u*4+g] = s2 + bih[n] + bhh[n];
    }
}

// ---------------- launch ----------------
extern "C" void kernel_launch(void* const* d_in, const int* in_sizes, int n_in,
                              void* d_out, int out_size)
{
    const int*   x    = (const int*)  d_in[0];
    const float* y    = (const float*)d_in[1];
    const float* emb  = (const float*)d_in[2];
    const float* yW   = (const float*)d_in[3];
    const float* yb   = (const float*)d_in[4];
    const float* Wih  = (const float*)d_in[5];
    const float* Whh  = (const float*)d_in[6];
    const float* bih  = (const float*)d_in[7];
    const float* bhh  = (const float*)d_in[8];
    const float* decW = (const float*)d_in[9];
    const float* decb = (const float*)d_in[10];
    float* out = (float*)d_out;

    __half *seq, *Wih_c, *Whh_c, *dW_c, *h0, *h1, *xgT, *embp, *Ep;
    float *wyv, *cbv;
    cudaGetSymbolAddress((void**)&seq,   g_seq);
    cudaGetSymbolAddress((void**)&xgT,   g_xgT);
    cudaGetSymbolAddress((void**)&h0,    g_h0);
    cudaGetSymbolAddress((void**)&h1,    g_h1);
    cudaGetSymbolAddress((void**)&Wih_c, g_Wih);
    cudaGetSymbolAddress((void**)&Whh_c, g_Whh);
    cudaGetSymbolAddress((void**)&dW_c,  g_dW);
    cudaGetSymbolAddress((void**)&embp,  g_embp);
    cudaGetSymbolAddress((void**)&Ep,    g_Ep);
    cudaGetSymbolAddress((void**)&wyv,   g_wyv);
    cudaGetSymbolAddress((void**)&cbv,   g_cbv);

    cudaFuncSetAttribute(gemm_mma, cudaFuncAttributeMaxDynamicSharedMemorySize, SMEMB);
    cudaFuncSetAttribute(lstm_persist, cudaFuncAttributeMaxDynamicSharedMemorySize, PS_SMEM);

    const int nW4 = 2*G4*Hsz/4;
    conv_kernel<<<(nW4+255)/256, 256>>>(Wih, Wih_c, nW4);
    conv_kernel<<<(nW4+255)/256, 256>>>(Whh, Whh_c, nW4);
    conv_kernel<<<(Vsz*Hsz/4+255)/256, 256>>>(decW, dW_c, Vsz*Hsz/4);
    conv_kernel<<<(513*Hsz/4+255)/256, 256>>>(emb, embp, 513*Hsz/4);
    prep_y<<<G4/8, 256>>>(Wih, yW, yb, bih, bhh, wyv, cbv);

    // E' = Wih0 · embp^T -> [tok][u][g] fp16
    gemm_mma<<<dim3(16, TOKP/128), 256, SMEMB>>>(
        Wih_c, embp, nullptr, nullptr, nullptr, Ep, TOKP, 1, 2);

    // ---- layer 0: recurrence with E' gather (writes seq t-major) ----
    reset_flags<<<1, 32>>>();
    lstm_persist<<<dim3(Hsz/16, Bsz/128), 256, PS_SMEM>>>(
        0, xgT, Ep, wyv, cbv, x, y, Whh_c, h0, h1, seq);

    // ---- layer 1: xg GEMM (contiguous t-major B rows) + recurrence ----
    gemm_mma<<<dim3(16, NBT/128), 256, SMEMB>>>(
        Wih_c + (size_t)G4*Hsz, seq, bih + G4, bhh + G4, nullptr, xgT, NBT, 1, 1);

    reset_flags<<<1, 32>>>();
    lstm_persist<<<dim3(Hsz/16, Bsz/128), 256, PS_SMEM>>>(
        1, xgT, Ep, wyv, cbv, x, y, Whh_c + (size_t)G4*Hsz, h0, h1, seq);

    // ---- decoder ----
    gemm_mma<<<dim3(Vsz/128, NBT/128), 256, SMEMB>>>(
        seq, dW_c, nullptr, nullptr, decb, out, Vsz, 0, 0);
}

// round 16
// speedup vs baseline: 1.1410x; 1.0304x over previous
#include <cuda_runtime.h>
#include <cuda_fp16.h>
#include <stdint.h>
#include <math.h>

#define Bsz 512
#define Tsz 128
#define Hsz 512
#define Vsz 512
#define NBT 65536
#define G4  2048
#define TOKP 640

// ---------------- device scratch ----------------
__device__ __align__(128) __half g_seq[(size_t)NBT*Hsz];      // [b][t][u]
__device__ __align__(128) __half g_xgT[(size_t)Tsz*G4*Bsz];   // [t][u][b][g] fp16
__device__ __align__(128) __half g_h0[Bsz*Hsz], g_h1[Bsz*Hsz];
__device__ __align__(128) __half g_Wih[2*(size_t)G4*Hsz];
__device__ __align__(128) __half g_Whh[2*(size_t)G4*Hsz];
__device__ __align__(128) __half g_dW[(size_t)Vsz*Hsz];
__device__ __align__(128) __half g_embp[TOKP*Hsz];
__device__ __align__(128) __half g_Ep[(size_t)TOKP*Hsz*4];    // E' [tok][u][g]
__device__ __align__(128) float  g_wyv[G4], g_cbv[G4];
__device__ unsigned g_flag[4][8];

// ---------------- helpers ----------------
__device__ __forceinline__ uint32_t smem_u32(const void* p){
    uint32_t a; asm("{ .reg .u64 t; cvta.to.shared.u64 t, %1; cvt.u32.u64 %0, t; }" : "=r"(a) : "l"(p)); return a;
}
#define CP16(dst, src) asm volatile("cp.async.cg.shared.global [%0], [%1], 16;" :: "r"(dst), "l"(src))
#define CPCOMMIT()     asm volatile("cp.async.commit_group;" ::: "memory")
#define CPWAIT(n)      asm volatile("cp.async.wait_group %0;" :: "n"(n) : "memory")
#define LDSM4(r, a) asm volatile("ldmatrix.sync.aligned.m8n8.x4.shared.b16 {%0,%1,%2,%3}, [%4];" \
    : "=r"((r)[0]),"=r"((r)[1]),"=r"((r)[2]),"=r"((r)[3]) : "r"(a))

__device__ __forceinline__ void mma16816(float* d, const uint32_t* a, const uint32_t* b){
    asm volatile("mma.sync.aligned.m16n8k16.row.col.f32.f16.f16.f32 "
        "{%0,%1,%2,%3}, {%4,%5,%6,%7}, {%8,%9}, {%0,%1,%2,%3};"
        : "+f"(d[0]), "+f"(d[1]), "+f"(d[2]), "+f"(d[3])
        : "r"(a[0]), "r"(a[1]), "r"(a[2]), "r"(a[3]), "r"(b[0]), "r"(b[1]));
}
__device__ __forceinline__ float fast_ex2(float x){ float r; asm("ex2.approx.f32 %0, %1;" : "=f"(r) : "f"(x)); return r; }
__device__ __forceinline__ float fast_rcp(float x){ float r; asm("rcp.approx.f32 %0, %1;" : "=f"(r) : "f"(x)); return r; }
__device__ __forceinline__ float fsig(float x){ return fast_rcp(1.f + fast_ex2(-1.4426950408889634f*x)); }
__device__ __forceinline__ float ftanh(float x){ return 2.f*fast_rcp(1.f + fast_ex2(-2.885390081777927f*x)) - 1.f; }

// ============ generic FF GEMM (fp16 operands, fp32 accum) ============
#define CHW 4608
#define STW 9216
#define SMEMB 110592   // 3 stages

__device__ __forceinline__ void load_chunk(uint32_t sbase,
    const __half* __restrict__ A, const __half* __restrict__ B,
    int m0, int n0, int ck, int bmap, int amap, int tid)
{
    #pragma unroll
    for (int i = tid; i < 1024; i += 256) {
        int r = i >> 3, q = i & 7;
        int arow = amap ? (((r >> 5) << 9) + m0 + (r & 31)) : (m0 + r);
        CP16(sbase + (r*36 + q*4)*4, A + (size_t)arow*Hsz + ck*64 + q*8);
    }
    #pragma unroll
    for (int i = tid; i < 1024; i += 256) {
        int r = i >> 3, q = i & 7;
        int brow;
        if (bmap == 0)      brow = n0 + r;
        else                { int c = n0 + r; brow = (c & 511)*Tsz + (c >> 9); }
        CP16(sbase + (CHW + r*36 + q*4)*4, B + (size_t)brow*Hsz + ck*64 + q*8);
    }
    CPCOMMIT();
}

__device__ __forceinline__ void compute_chunk(uint32_t stg,
    float acc[4][4][4], int lane, int wm, int wn)
{
    int laneA_r = lane & 15;
    int laneA_c = (lane >> 4) * 4;
    int laneB_r = (lane & 7) + ((lane >> 4) << 3);
    int laneB_c = ((lane >> 3) & 1) * 4;
    #pragma unroll
    for (int ks = 0; ks < 4; ks++) {
        int kw = ks*8;
        uint32_t ah[4][4], bh[2][4];
        #pragma unroll
        for (int mt = 0; mt < 4; mt++) {
            uint32_t aw = (uint32_t)(wm*64 + mt*16 + laneA_r)*36 + kw + laneA_c;
            LDSM4(ah[mt], stg + aw*4);
        }
        #pragma unroll
        for (int np = 0; np < 2; np++) {
            uint32_t bw = (uint32_t)(wn*32 + np*16 + laneB_r)*36 + kw + laneB_c;
            LDSM4(bh[np], stg + (CHW + bw)*4);
        }
        #pragma unroll
        for (int mt = 0; mt < 4; mt++)
        #pragma unroll
        for (int nt = 0; nt < 4; nt++)
            mma16816(acc[mt][nt], ah[mt], &bh[nt>>1][(nt&1)*2]);
    }
}

// cmode: 0 fp32 row-major out; 1 xgT [t][u][b][g]; 2 E' [tok][u][g]
__global__ void __launch_bounds__(256,2)
gemm_mma(const __half* __restrict__ A, const __half* __restrict__ B,
         const float* __restrict__ br1, const float* __restrict__ br2,
         const float* __restrict__ bcn, void* __restrict__ Cv,
         int Ntot, int bmap, int mx, int cmode)
{
    extern __shared__ uint32_t sm[];
    uint32_t sbase = smem_u32(sm);
    int tid = threadIdx.x, lane = tid & 31, wid = tid >> 5;
    int wm = wid >> 2, wn = wid & 3;
    int bm = mx ? blockIdx.x : blockIdx.y;
    int bn = mx ? blockIdx.y : blockIdx.x;
    int m0 = cmode ? bm*32 : bm*128;
    int n0 = bn*128;
    int amap = (cmode != 0);

    float acc[4][4][4];
    #pragma unroll
    for (int a = 0; a < 4; a++)
    #pragma unroll
    for (int b = 0; b < 4; b++)
    #pragma unroll
    for (int cc = 0; cc < 4; cc++) acc[a][b][cc] = 0.f;

    load_chunk(sbase, A, B, m0, n0, 0, bmap, amap, tid);
    int st = 0, nst = 1;
    for (int k = 0; k < 8; k++) {
        if (k < 7) {
            load_chunk(sbase + nst*STW*4, A, B, m0, n0, k+1, bmap, amap, tid);
            CPWAIT(1);
        } else {
            CPWAIT(0);
        }
        __syncthreads();
        compute_chunk(sbase + st*STW*4, acc, lane, wm, wn);
        st = nst; nst = (nst + 1 == 3) ? 0 : nst + 1;
    }

    if (cmode) {
        // ---- transpose epilogue: SMEM [ul(32)][cloc(128,pad132)][g(4)] halves ----
        __syncthreads();
        __half* sx = (__half*)sm;
        #pragma unroll
        for (int mt = 0; mt < 4; mt++) {
            #pragma unroll
            for (int half = 0; half < 2; half++) {
                int rloc = wm*64 + mt*16 + (lane >> 2) + half*8;
                int g = rloc >> 5, ul = rloc & 31;
                int nrow = (g << 9) + m0 + ul;
                float rb = br1 ? (br1[nrow] + br2[nrow]) : 0.f;
                #pragma unroll
                for (int nt = 0; nt < 4; nt++) {
                    int cloc = wn*32 + nt*8 + (lane & 3)*2;
                    sx[(ul*132 + cloc)*4 + g]     = __float2half_rn(acc[mt][nt][half*2+0] + rb);
                    sx[(ul*132 + cloc + 1)*4 + g] = __float2half_rn(acc[mt][nt][half*2+1] + rb);
                }
            }
        }
        __syncthreads();
        if (cmode == 1) {
            int t = n0 >> 9, bwin = n0 & 511;
            #pragma unroll
            for (int i = tid; i < 4096; i += 256) {
                int ul = i >> 7, bl = i & 127;
                uint2 v = *(uint2*)&sx[(ul*132 + bl)*4];
                *(uint2*)((__half*)Cv + (((size_t)t*512 + m0 + ul)*512 + bwin + bl)*4) = v;
            }
        } else {
            #pragma unroll
            for (int i = tid; i < 4096; i += 256) {
                int tkl = i >> 5, ul = i & 31;
                uint2 v = *(uint2*)&sx[(ul*132 + tkl)*4];
                *(uint2*)((__half*)Cv + (((size_t)(n0 + tkl))*512 + m0 + ul)*4) = v;
            }
        }
        return;
    }

    #pragma unroll
    for (int mt = 0; mt < 4; mt++) {
        #pragma unroll
        for (int half = 0; half < 2; half++) {
            int m = m0 + wm*64 + mt*16 + (lane >> 2) + half*8;
            float rb = br1 ? (br1[m] + br2[m]) : 0.f;
            #pragma unroll
            for (int nt = 0; nt < 4; nt++) {
                int c = n0 + wn*32 + nt*8 + (lane & 3)*2;
                float v0 = acc[mt][nt][half*2+0] + rb;
                float v1 = acc[mt][nt][half*2+1] + rb;
                if (bcn) { v0 += bcn[c]; v1 += bcn[c+1]; }
                *(float2*)((float*)Cv + (size_t)m*Ntot + c) = make_float2(v0, v1);
            }
        }
    }
}

// ============ persistent LSTM recurrence ============
#define PS_SMEM 129536
__device__ __forceinline__ int WOFFf(int ck,int r){ return (ck*64 + r)*36; }
__device__ __forceinline__ int HOFFf(int st,int r){ return 18432 + (st*128 + r)*36; }

__global__ void reset_flags(){ int i = threadIdx.x; if (i < 32) ((unsigned*)g_flag)[i] = 0u; }

// mode 0: layer 0 — gates from E' gather + rank-1 y term
// mode 1: layer 1 — gates from xgT [t][u][b][g]
__global__ void __launch_bounds__(256,1)
lstm_persist(int mode, const __half* __restrict__ xg,
             const __half* __restrict__ Ep,
             const float* __restrict__ wyv, const float* __restrict__ cbv,
             const int* __restrict__ xtok, const float* __restrict__ yv,
             const __half* __restrict__ W,
             __half* __restrict__ h0, __half* __restrict__ h1,
             __half* __restrict__ seq)
{
    extern __shared__ uint32_t sm[];
    uint32_t sb = smem_u32(sm);
    int tid = threadIdx.x, lane = tid & 31, w = tid >> 5;
    int laneR = lane >> 2, laneC = lane & 3;
    int u0 = blockIdx.x * 16;
    int b0 = blockIdx.y * 128;
    int gid = blockIdx.y;
    int myck = u0 >> 6;

    int laneA_r = lane & 15;
    int laneA_c = (lane >> 4) * 4;
    int laneB_r = (lane & 7) + ((lane >> 4) << 3);
    int laneB_c = ((lane >> 3) & 1) * 4;

    // ---- persistent W tile ----
    for (int i = tid; i < 4096; i += 256) {
        int ck = i >> 9, rem = i & 511;
        int r = rem >> 3, q = rem & 7;
        int g = r >> 4, ul = r & 15;
        CP16(sb + (WOFFf(ck,r) + q*4)*4,
             W + ((size_t)(g*Hsz + u0 + ul))*Hsz + ck*64 + q*8);
    }
    CPCOMMIT(); CPWAIT(0);
    __syncthreads();

    // ---- mode 0: per-thread constant y-conditioning term ----
    float ybase[2][16];
    if (mode == 0) {
        #pragma unroll
        for (int half = 0; half < 2; half++) {
            int b = b0 + w*16 + laneR + half*8;
            float yy = yv[b];
            #pragma unroll
            for (int uh = 0; uh < 2; uh++)
            #pragma unroll
            for (int du = 0; du < 2; du++) {
                int u = u0 + laneC*2 + uh*8 + du;
                float4 wv = *(const float4*)(wyv + u*4);
                float4 cv = *(const float4*)(cbv + u*4);
                ybase[half][uh*8+du*4+0] = yy*wv.x + cv.x;
                ybase[half][uh*8+du*4+1] = yy*wv.y + cv.y;
                ybase[half][uh*8+du*4+2] = yy*wv.z + cv.z;
                ybase[half][uh*8+du*4+3] = yy*wv.w + cv.w;
            }
        }
    }

    __half* hb[2] = {h0, h1};
    float creg[2][2][2];
    #pragma unroll
    for (int a = 0; a < 2; a++)
    #pragma unroll
    for (int b = 0; b < 2; b++) { creg[a][b][0] = 0.f; creg[a][b][1] = 0.f; }

    for (int t = 0; t < Tsz; t++) {
        const __half* Hc = hb[t & 1];
        __half* Nx = hb[(t+1) & 1];
        unsigned tgt = 4u * (unsigned)t;

        float xv[2][16];
        if (mode == 0) {
            #pragma unroll
            for (int half = 0; half < 2; half++) {
                int b = b0 + w*16 + laneR + half*8;
                int tok = (t == 0) ? Vsz : xtok[b*Tsz + t - 1];
                #pragma unroll
                for (int uh = 0; uh < 2; uh++) {
                    int u = u0 + laneC*2 + uh*8;
                    uint4 v = *(const uint4*)(Ep + ((size_t)tok*Hsz + u)*4);
                    __half2 p0 = *(__half2*)&v.x, p1 = *(__half2*)&v.y;
                    __half2 p2 = *(__half2*)&v.z, p3 = *(__half2*)&v.w;
                    xv[half][uh*8+0] = __half2float(p0.x) + ybase[half][uh*8+0];
                    xv[half][uh*8+1] = __half2float(p0.y) + ybase[half][uh*8+1];
                    xv[half][uh*8+2] = __half2float(p1.x) + ybase[half][uh*8+2];
                    xv[half][uh*8+3] = __half2float(p1.y) + ybase[half][uh*8+3];
                    xv[half][uh*8+4] = __half2float(p2.x) + ybase[half][uh*8+4];
                    xv[half][uh*8+5] = __half2float(p2.y) + ybase[half][uh*8+5];
                    xv[half][uh*8+6] = __half2float(p3.x) + ybase[half][uh*8+6];
                    xv[half][uh*8+7] = __half2float(p3.y) + ybase[half][uh*8+7];
                }
            }
        } else {
            const __half* xgt = xg + (size_t)t*G4*Bsz;
            #pragma unroll
            for (int half = 0; half < 2; half++) {
                int b = b0 + w*16 + laneR + half*8;
                #pragma unroll
                for (int uh = 0; uh < 2; uh++)
                #pragma unroll
                for (int du = 0; du < 2; du++) {
                    int u = u0 + laneC*2 + uh*8 + du;
                    uint2 v = *(const uint2*)(xgt + ((size_t)u*512 + b)*4);
                    __half2 p0 = *(__half2*)&v.x;
                    __half2 p1 = *(__half2*)&v.y;
                    xv[half][uh*8+du*4+0] = __half2float(p0.x);
                    xv[half][uh*8+du*4+1] = __half2float(p0.y);
                    xv[half][uh*8+du*4+2] = __half2float(p1.x);
                    xv[half][uh*8+du*4+3] = __half2float(p1.y);
                }
            }
        }

        float acc[8][4];
        #pragma unroll
        for (int i = 0; i < 8; i++)
        #pragma unroll
        for (int j = 0; j < 4; j++) acc[i][j] = 0.f;

        if (t > 0) {
            auto wait_ck = [&](int ck){
                unsigned v;
                do { asm volatile("ld.acquire.gpu.global.u32 %0, [%1];"
                                  : "=r"(v) : "l"(&g_flag[gid][ck])); } while (v < tgt);
            };
            auto ldh = [&](int ck, int st){
                #pragma unroll
                for (int i = tid; i < 1024; i += 256) {
                    int r = i >> 3, q = i & 7;
                    CP16(sb + (HOFFf(st,r) + q*4)*4,
                         Hc + (size_t)(b0 + r)*Hsz + ck*64 + q*8);
                }
                CPCOMMIT();
            };

            wait_ck(0);
            ldh(0, 0);
            int st = 0, nst = 1;
            for (int ck = 0; ck < 8; ck++) {
                if (ck < 7) { wait_ck(ck+1); ldh(ck+1, nst); CPWAIT(1); }
                else        { CPWAIT(0); }
                __syncthreads();
                #pragma unroll
                for (int ks = 0; ks < 4; ks++) {
                    int kw = ks*8;
                    uint32_t ah[4], bh[4][4];
                    uint32_t aw = (uint32_t)(HOFFf(st, w*16 + laneA_r)) + kw + laneA_c;
                    LDSM4(ah, sb + aw*4);
                    #pragma unroll
                    for (int np = 0; np < 4; np++) {
                        uint32_t bw = (uint32_t)(WOFFf(ck, np*16 + laneB_r)) + kw + laneB_c;
                        LDSM4(bh[np], sb + bw*4);
                    }
                    #pragma unroll
                    for (int nt = 0; nt < 8; nt++)
                        mma16816(acc[nt], ah, &bh[nt>>1][(nt&1)*2]);
                }
                st = nst; nst = (nst + 1 == 3) ? 0 : nst + 1;
            }
        }

        // epilogue: gates + state update (c in registers, fast transcendentals)
        #pragma unroll
        for (int half = 0; half < 2; half++) {
            int b = b0 + w*16 + laneR + half*8;
            #pragma unroll
            for (int uh = 0; uh < 2; uh++) {
                float hn[2];
                #pragma unroll
                for (int du = 0; du < 2; du++) {
                    int q = half*2 + du;
                    float gi = acc[0*2+uh][q] + xv[half][uh*8+du*4+0];
                    float gf = acc[1*2+uh][q] + xv[half][uh*8+du*4+1];
                    float gg = acc[2*2+uh][q] + xv[half][uh*8+du*4+2];
                    float go = acc[3*2+uh][q] + xv[half][uh*8+du*4+3];
                    float is = fsig(gi);
                    float fs = fsig(gf);
                    float os = fsig(go);
                    float gt = ftanh(gg);
                    float cn = fs*creg[half][uh][du] + is*gt;
                    creg[half][uh][du] = cn;
                    hn[du] = os*ftanh(cn);
                }
                int u2 = u0 + laneC*2 + uh*8;
                __half2 hp;
                hp.x = __float2half_rn(hn[0]);
                hp.y = __float2half_rn(hn[1]);
                *(__half2*)(Nx + (size_t)b*Hsz + u2) = hp;
                *(__half2*)(seq + ((size_t)b*Tsz + t)*Hsz + u2) = hp;
            }
        }

        if (t < Tsz - 1) {
            __threadfence();
            __syncthreads();
            if (tid == 0) atomicAdd(&g_flag[gid][myck], 1u);
        }
    }
}

// ---------------- merged fp32->fp16 conversion (Wih | Whh | decW | emb) ----------------
#define N4_W   524288                       // 2*G4*Hsz/4
#define N4_D   65536                        // Vsz*Hsz/4
#define N4_E   65664                        // 513*Hsz/4
#define N4_ALL (N4_W + N4_W + N4_D + N4_E)
__global__ void conv_all(const float* __restrict__ Wih, const float* __restrict__ Whh,
                         const float* __restrict__ decW, const float* __restrict__ emb,
                         __half* __restrict__ oW, __half* __restrict__ oH,
                         __half* __restrict__ oD, __half* __restrict__ oE)
{
    int i = blockIdx.x*256 + threadIdx.x;
    if (i >= N4_ALL) return;
    const float* s; __half* d; int j;
    if (i < N4_W)                 { s = Wih;  d = oW; j = i; }
    else if (i < 2*N4_W)          { s = Whh;  d = oH; j = i - N4_W; }
    else if (i < 2*N4_W + N4_D)   { s = decW; d = oD; j = i - 2*N4_W; }
    else                          { s = emb;  d = oE; j = i - 2*N4_W - N4_D; }
    float4 v = ((const float4*)s)[j];
    __half2 a, b;
    a.x = __float2half_rn(v.x); a.y = __float2half_rn(v.y);
    b.x = __float2half_rn(v.z); b.y = __float2half_rn(v.w);
    ((__half2*)d)[j*2]   = a;
    ((__half2*)d)[j*2+1] = b;
}

// wy[u*4+g] = Wih0[n]·yW ; cb[u*4+g] = Wih0[n]·yb + bih0[n] + bhh0[n],  n = g*512+u
__global__ void prep_y(const float* __restrict__ Wih, const float* __restrict__ yW,
                       const float* __restrict__ yb, const float* __restrict__ bih,
                       const float* __restrict__ bhh,
                       float* __restrict__ wyv, float* __restrict__ cbv)
{
    int n = blockIdx.x*8 + (threadIdx.x >> 5);
    int lane = threadIdx.x & 31;
    const float* wr = Wih + (size_t)n*Hsz;
    float s1 = 0.f, s2 = 0.f;
    for (int k = lane; k < Hsz; k += 32) { float wv = wr[k]; s1 += wv*yW[k]; s2 += wv*yb[k]; }
    #pragma unroll
    for (int o = 16; o; o >>= 1) {
        s1 += __shfl_down_sync(0xFFFFFFFFu, s1, o);
        s2 += __shfl_down_sync(0xFFFFFFFFu, s2, o);
    }
    if (lane == 0) {
        int g = n >> 9, u = n & 511;
        wyv[u*4+g] = s1;
        cbv[u*4+g] = s2 + bih[n] + bhh[n];
    }
}

// ---------------- launch ----------------
extern "C" void kernel_launch(void* const* d_in, const int* in_sizes, int n_in,
                              void* d_out, int out_size)
{
    const int*   x    = (const int*)  d_in[0];
    const float* y    = (const float*)d_in[1];
    const float* emb  = (const float*)d_in[2];
    const float* yW   = (const float*)d_in[3];
    const float* yb   = (const float*)d_in[4];
    const float* Wih  = (const float*)d_in[5];
    const float* Whh  = (const float*)d_in[6];
    const float* bih  = (const float*)d_in[7];
    const float* bhh  = (const float*)d_in[8];
    const float* decW = (const float*)d_in[9];
    const float* decb = (const float*)d_in[10];
    float* out = (float*)d_out;

    __half *seq, *Wih_c, *Whh_c, *dW_c, *h0, *h1, *xgT, *embp, *Ep;
    float *wyv, *cbv;
    cudaGetSymbolAddress((void**)&seq,   g_seq);
    cudaGetSymbolAddress((void**)&xgT,   g_xgT);
    cudaGetSymbolAddress((void**)&h0,    g_h0);
    cudaGetSymbolAddress((void**)&h1,    g_h1);
    cudaGetSymbolAddress((void**)&Wih_c, g_Wih);
    cudaGetSymbolAddress((void**)&Whh_c, g_Whh);
    cudaGetSymbolAddress((void**)&dW_c,  g_dW);
    cudaGetSymbolAddress((void**)&embp,  g_embp);
    cudaGetSymbolAddress((void**)&Ep,    g_Ep);
    cudaGetSymbolAddress((void**)&wyv,   g_wyv);
    cudaGetSymbolAddress((void**)&cbv,   g_cbv);

    cudaFuncSetAttribute(gemm_mma, cudaFuncAttributeMaxDynamicSharedMemorySize, SMEMB);
    cudaFuncSetAttribute(lstm_persist, cudaFuncAttributeMaxDynamicSharedMemorySize, PS_SMEM);

    // merged conversions + y-term prep
    conv_all<<<(N4_ALL + 255)/256, 256>>>(Wih, Whh, decW, emb, Wih_c, Whh_c, dW_c, embp);
    prep_y<<<G4/8, 256>>>(Wih, yW, yb, bih, bhh, wyv, cbv);

    // E' = Wih0 · embp^T -> [tok][u][g] fp16
    gemm_mma<<<dim3(16, TOKP/128), 256, SMEMB>>>(
        Wih_c, embp, nullptr, nullptr, nullptr, Ep, TOKP, 0, 1, 2);

    // ---- layer 0: recurrence with E' gather (no xg GEMM) ----
    reset_flags<<<1, 32>>>();
    lstm_persist<<<dim3(Hsz/16, Bsz/128), 256, PS_SMEM>>>(
        0, xgT, Ep, wyv, cbv, x, y, Whh_c, h0, h1, seq);

    // ---- layer 1: xg GEMM + recurrence ----
    gemm_mma<<<dim3(16, NBT/128), 256, SMEMB>>>(
        Wih_c + (size_t)G4*Hsz, seq, bih + G4, bhh + G4, nullptr, xgT, NBT, 1, 1, 1);

    reset_flags<<<1, 32>>>();
    lstm_persist<<<dim3(Hsz/16, Bsz/128), 256, PS_SMEM>>>(
        1, xgT, Ep, wyv, cbv, x, y, Whh_c + (size_t)G4*Hsz, h0, h1, seq);

    // ---- decoder ----
    gemm_mma<<<dim3(Vsz/128, NBT/128), 256, SMEMB>>>(
        seq, dW_c, nullptr, nullptr, decb, out, Vsz, 0, 0, 0);
}

// round 17
// speedup vs baseline: 1.3210x; 1.1577x over previous
#include <cuda_runtime.h>
#include <cuda_fp16.h>
#include <stdint.h>
#include <math.h>

#define Bsz 512
#define Tsz 128
#define Hsz 512
#define Vsz 512
#define NBT 65536
#define G4  2048
#define TOKP 640

// ---------------- device scratch ----------------
__device__ __align__(128) __half g_seq[(size_t)NBT*Hsz];      // [b][t][u]
__device__ __align__(128) __half g_xgT[(size_t)Tsz*G4*Bsz];   // [t][u][b][g] fp16
__device__ __align__(128) __half g_h0[Bsz*Hsz], g_h1[Bsz*Hsz];
__device__ __align__(128) __half g_Wih[2*(size_t)G4*Hsz];
__device__ __align__(128) __half g_Whh[2*(size_t)G4*Hsz];
__device__ __align__(128) __half g_dW[(size_t)Vsz*Hsz];
__device__ __align__(128) __half g_embp[TOKP*Hsz];
__device__ __align__(128) __half g_Ep[(size_t)TOKP*Hsz*4];    // E' [tok][u][g]
__device__ __align__(128) float  g_wyv[G4], g_cbv[G4];
__device__ unsigned g_flag[4][4];   // [b-group][u-chunk(128u)], monotonic

// ---------------- helpers ----------------
__device__ __forceinline__ uint32_t smem_u32(const void* p){
    uint32_t a; asm("{ .reg .u64 t; cvta.to.shared.u64 t, %1; cvt.u32.u64 %0, t; }" : "=r"(a) : "l"(p)); return a;
}
#define CP16(dst, src) asm volatile("cp.async.cg.shared.global [%0], [%1], 16;" :: "r"(dst), "l"(src))
#define CPCOMMIT()     asm volatile("cp.async.commit_group;" ::: "memory")
#define CPWAIT(n)      asm volatile("cp.async.wait_group %0;" :: "n"(n) : "memory")
#define LDSM4(r, a) asm volatile("ldmatrix.sync.aligned.m8n8.x4.shared.b16 {%0,%1,%2,%3}, [%4];" \
    : "=r"((r)[0]),"=r"((r)[1]),"=r"((r)[2]),"=r"((r)[3]) : "r"(a))

__device__ __forceinline__ void mma16816(float* d, const uint32_t* a, const uint32_t* b){
    asm volatile("mma.sync.aligned.m16n8k16.row.col.f32.f16.f16.f32 "
        "{%0,%1,%2,%3}, {%4,%5,%6,%7}, {%8,%9}, {%0,%1,%2,%3};"
        : "+f"(d[0]), "+f"(d[1]), "+f"(d[2]), "+f"(d[3])
        : "r"(a[0]), "r"(a[1]), "r"(a[2]), "r"(a[3]), "r"(b[0]), "r"(b[1]));
}
__device__ __forceinline__ float fast_ex2(float x){ float r; asm("ex2.approx.f32 %0, %1;" : "=f"(r) : "f"(x)); return r; }
__device__ __forceinline__ float fast_rcp(float x){ float r; asm("rcp.approx.f32 %0, %1;" : "=f"(r) : "f"(x)); return r; }
__device__ __forceinline__ float fsig(float x){ return fast_rcp(1.f + fast_ex2(-1.4426950408889634f*x)); }
__device__ __forceinline__ float ftanh(float x){ return 2.f*fast_rcp(1.f + fast_ex2(-2.885390081777927f*x)) - 1.f; }

// ============ generic FF GEMM (fp16 operands, fp32 accum) ============
#define CHW 4608
#define STW 9216
#define SMEMB 110592   // 3 stages

__device__ __forceinline__ void load_chunk(uint32_t sbase,
    const __half* __restrict__ A, const __half* __restrict__ B,
    int m0, int n0, int ck, int bmap, int amap, int tid)
{
    #pragma unroll
    for (int i = tid; i < 1024; i += 256) {
        int r = i >> 3, q = i & 7;
        int arow = amap ? (((r >> 5) << 9) + m0 + (r & 31)) : (m0 + r);
        CP16(sbase + (r*36 + q*4)*4, A + (size_t)arow*Hsz + ck*64 + q*8);
    }
    #pragma unroll
    for (int i = tid; i < 1024; i += 256) {
        int r = i >> 3, q = i & 7;
        int brow;
        if (bmap == 0)      brow = n0 + r;
        else                { int c = n0 + r; brow = (c & 511)*Tsz + (c >> 9); }
        CP16(sbase + (CHW + r*36 + q*4)*4, B + (size_t)brow*Hsz + ck*64 + q*8);
    }
    CPCOMMIT();
}

__device__ __forceinline__ void compute_chunk(uint32_t stg,
    float acc[4][4][4], int lane, int wm, int wn)
{
    int laneA_r = lane & 15;
    int laneA_c = (lane >> 4) * 4;
    int laneB_r = (lane & 7) + ((lane >> 4) << 3);
    int laneB_c = ((lane >> 3) & 1) * 4;
    #pragma unroll
    for (int ks = 0; ks < 4; ks++) {
        int kw = ks*8;
        uint32_t ah[4][4], bh[2][4];
        #pragma unroll
        for (int mt = 0; mt < 4; mt++) {
            uint32_t aw = (uint32_t)(wm*64 + mt*16 + laneA_r)*36 + kw + laneA_c;
            LDSM4(ah[mt], stg + aw*4);
        }
        #pragma unroll
        for (int np = 0; np < 2; np++) {
            uint32_t bw = (uint32_t)(wn*32 + np*16 + laneB_r)*36 + kw + laneB_c;
            LDSM4(bh[np], stg + (CHW + bw)*4);
        }
        #pragma unroll
        for (int mt = 0; mt < 4; mt++)
        #pragma unroll
        for (int nt = 0; nt < 4; nt++)
            mma16816(acc[mt][nt], ah[mt], &bh[nt>>1][(nt&1)*2]);
    }
}

// cmode: 0 fp32 row-major out; 1 xgT [t][u][b][g]; 2 E' [tok][u][g]
__global__ void __launch_bounds__(256,2)
gemm_mma(const __half* __restrict__ A, const __half* __restrict__ B,
         const float* __restrict__ br1, const float* __restrict__ br2,
         const float* __restrict__ bcn, void* __restrict__ Cv,
         int Ntot, int bmap, int mx, int cmode)
{
    extern __shared__ uint32_t sm[];
    uint32_t sbase = smem_u32(sm);
    int tid = threadIdx.x, lane = tid & 31, wid = tid >> 5;
    int wm = wid >> 2, wn = wid & 3;
    int bm = mx ? blockIdx.x : blockIdx.y;
    int bn = mx ? blockIdx.y : blockIdx.x;
    int m0 = cmode ? bm*32 : bm*128;
    int n0 = bn*128;
    int amap = (cmode != 0);

    float acc[4][4][4];
    #pragma unroll
    for (int a = 0; a < 4; a++)
    #pragma unroll
    for (int b = 0; b < 4; b++)
    #pragma unroll
    for (int cc = 0; cc < 4; cc++) acc[a][b][cc] = 0.f;

    load_chunk(sbase, A, B, m0, n0, 0, bmap, amap, tid);
    int st = 0, nst = 1;
    for (int k = 0; k < 8; k++) {
        if (k < 7) {
            load_chunk(sbase + nst*STW*4, A, B, m0, n0, k+1, bmap, amap, tid);
            CPWAIT(1);
        } else {
            CPWAIT(0);
        }
        __syncthreads();
        compute_chunk(sbase + st*STW*4, acc, lane, wm, wn);
        st = nst; nst = (nst + 1 == 3) ? 0 : nst + 1;
    }

    if (cmode) {
        // ---- transpose epilogue: SMEM [ul(32)][cloc(128,pad132)][g(4)] halves ----
        __syncthreads();
        __half* sx = (__half*)sm;
        #pragma unroll
        for (int mt = 0; mt < 4; mt++) {
            #pragma unroll
            for (int half = 0; half < 2; half++) {
                int rloc = wm*64 + mt*16 + (lane >> 2) + half*8;
                int g = rloc >> 5, ul = rloc & 31;
                int nrow = (g << 9) + m0 + ul;
                float rb = br1 ? (br1[nrow] + br2[nrow]) : 0.f;
                #pragma unroll
                for (int nt = 0; nt < 4; nt++) {
                    int cloc = wn*32 + nt*8 + (lane & 3)*2;
                    sx[(ul*132 + cloc)*4 + g]     = __float2half_rn(acc[mt][nt][half*2+0] + rb);
                    sx[(ul*132 + cloc + 1)*4 + g] = __float2half_rn(acc[mt][nt][half*2+1] + rb);
                }
            }
        }
        __syncthreads();
        if (cmode == 1) {
            int t = n0 >> 9, bwin = n0 & 511;
            #pragma unroll
            for (int i = tid; i < 4096; i += 256) {
                int ul = i >> 7, bl = i & 127;
                uint2 v = *(uint2*)&sx[(ul*132 + bl)*4];
                *(uint2*)((__half*)Cv + (((size_t)t*512 + m0 + ul)*512 + bwin + bl)*4) = v;
            }
        } else {
            #pragma unroll
            for (int i = tid; i < 4096; i += 256) {
                int tkl = i >> 5, ul = i & 31;
                uint2 v = *(uint2*)&sx[(ul*132 + tkl)*4];
                *(uint2*)((__half*)Cv + (((size_t)(n0 + tkl))*512 + m0 + ul)*4) = v;
            }
        }
        return;
    }

    #pragma unroll
    for (int mt = 0; mt < 4; mt++) {
        #pragma unroll
        for (int half = 0; half < 2; half++) {
            int m = m0 + wm*64 + mt*16 + (lane >> 2) + half*8;
            float rb = br1 ? (br1[m] + br2[m]) : 0.f;
            #pragma unroll
            for (int nt = 0; nt < 4; nt++) {
                int c = n0 + wn*32 + nt*8 + (lane & 3)*2;
                float v0 = acc[mt][nt][half*2+0] + rb;
                float v1 = acc[mt][nt][half*2+1] + rb;
                if (bcn) { v0 += bcn[c]; v1 += bcn[c+1]; }
                *(float2*)((float*)Cv + (size_t)m*Ntot + c) = make_float2(v0, v1);
            }
        }
    }
}

// ============ persistent LSTM recurrence (BK=128, release-atomic publish) ============
// SMEM: W 4ck x 64r x 68w = 69632B; H 3st x 128r x 68w = 104448B -> 174080B
#define PS_SMEM 174080
__device__ __forceinline__ int WOFFf(int ck,int r){ return (ck*64 + r)*68; }
__device__ __forceinline__ int HOFFf(int st,int r){ return 17408 + (st*128 + r)*68; }

__global__ void reset_flags(){ int i = threadIdx.x; if (i < 16) ((unsigned*)g_flag)[i] = 0u; }

// mode 0: layer 0 — gates from E' gather + rank-1 y term
// mode 1: layer 1 — gates from xgT [t][u][b][g]
__global__ void __launch_bounds__(256,1)
lstm_persist(int mode, const __half* __restrict__ xg,
             const __half* __restrict__ Ep,
             const float* __restrict__ wyv, const float* __restrict__ cbv,
             const int* __restrict__ xtok, const float* __restrict__ yv,
             const __half* __restrict__ W,
             __half* __restrict__ h0, __half* __restrict__ h1,
             __half* __restrict__ seq)
{
    extern __shared__ uint32_t sm[];
    uint32_t sb = smem_u32(sm);
    int tid = threadIdx.x, lane = tid & 31, w = tid >> 5;
    int laneR = lane >> 2, laneC = lane & 3;
    int u0 = blockIdx.x * 16;
    int b0 = blockIdx.y * 128;
    int gid = blockIdx.y;
    int myck = u0 >> 7;                 // 4 u-chunks of 128 units

    int laneA_r = lane & 15;
    int laneA_c = (lane >> 4) * 4;
    int laneB_r = (lane & 7) + ((lane >> 4) << 3);
    int laneB_c = ((lane >> 3) & 1) * 4;

    // ---- persistent W tile: 4 chunks x 64 gate-rows x 128 halves ----
    for (int i = tid; i < 4096; i += 256) {
        int ck = i >> 10, rem = i & 1023;
        int r = rem >> 4, q = rem & 15;
        int g = r >> 4, ul = r & 15;
        CP16(sb + (WOFFf(ck,r) + q*4)*4,
             W + ((size_t)(g*Hsz + u0 + ul))*Hsz + ck*128 + q*8);
    }
    CPCOMMIT(); CPWAIT(0);
    __syncthreads();

    // ---- mode 0: per-thread constant y-conditioning term ----
    float ybase[2][16];
    if (mode == 0) {
        #pragma unroll
        for (int half = 0; half < 2; half++) {
            int b = b0 + w*16 + laneR + half*8;
            float yy = yv[b];
            #pragma unroll
            for (int uh = 0; uh < 2; uh++)
            #pragma unroll
            for (int du = 0; du < 2; du++) {
                int u = u0 + laneC*2 + uh*8 + du;
                float4 wv = *(const float4*)(wyv + u*4);
                float4 cv = *(const float4*)(cbv + u*4);
                ybase[half][uh*8+du*4+0] = yy*wv.x + cv.x;
                ybase[half][uh*8+du*4+1] = yy*wv.y + cv.y;
                ybase[half][uh*8+du*4+2] = yy*wv.z + cv.z;
                ybase[half][uh*8+du*4+3] = yy*wv.w + cv.w;
            }
        }
    }

    __half* hb[2] = {h0, h1};
    float creg[2][2][2];
    #pragma unroll
    for (int a = 0; a < 2; a++)
    #pragma unroll
    for (int b = 0; b < 2; b++) { creg[a][b][0] = 0.f; creg[a][b][1] = 0.f; }

    for (int t = 0; t < Tsz; t++) {
        const __half* Hc = hb[t & 1];
        __half* Nx = hb[(t+1) & 1];
        unsigned tgt = 8u * (unsigned)t;

        float xv[2][16];
        if (mode == 0) {
            #pragma unroll
            for (int half = 0; half < 2; half++) {
                int b = b0 + w*16 + laneR + half*8;
                int tok = (t == 0) ? Vsz : xtok[b*Tsz + t - 1];
                #pragma unroll
                for (int uh = 0; uh < 2; uh++) {
                    int u = u0 + laneC*2 + uh*8;
                    uint4 v = *(const uint4*)(Ep + ((size_t)tok*Hsz + u)*4);
                    __half2 p0 = *(__half2*)&v.x, p1 = *(__half2*)&v.y;
                    __half2 p2 = *(__half2*)&v.z, p3 = *(__half2*)&v.w;
                    xv[half][uh*8+0] = __half2float(p0.x) + ybase[half][uh*8+0];
                    xv[half][uh*8+1] = __half2float(p0.y) + ybase[half][uh*8+1];
                    xv[half][uh*8+2] = __half2float(p1.x) + ybase[half][uh*8+2];
                    xv[half][uh*8+3] = __half2float(p1.y) + ybase[half][uh*8+3];
                    xv[half][uh*8+4] = __half2float(p2.x) + ybase[half][uh*8+4];
                    xv[half][uh*8+5] = __half2float(p2.y) + ybase[half][uh*8+5];
                    xv[half][uh*8+6] = __half2float(p3.x) + ybase[half][uh*8+6];
                    xv[half][uh*8+7] = __half2float(p3.y) + ybase[half][uh*8+7];
                }
            }
        } else {
            const __half* xgt = xg + (size_t)t*G4*Bsz;
            #pragma unroll
            for (int half = 0; half < 2; half++) {
                int b = b0 + w*16 + laneR + half*8;
                #pragma unroll
                for (int uh = 0; uh < 2; uh++)
                #pragma unroll
                for (int du = 0; du < 2; du++) {
                    int u = u0 + laneC*2 + uh*8 + du;
                    uint2 v = *(const uint2*)(xgt + ((size_t)u*512 + b)*4);
                    __half2 p0 = *(__half2*)&v.x;
                    __half2 p1 = *(__half2*)&v.y;
                    xv[half][uh*8+du*4+0] = __half2float(p0.x);
                    xv[half][uh*8+du*4+1] = __half2float(p0.y);
                    xv[half][uh*8+du*4+2] = __half2float(p1.x);
                    xv[half][uh*8+du*4+3] = __half2float(p1.y);
                }
            }
        }

        float acc[8][4];
        #pragma unroll
        for (int i = 0; i < 8; i++)
        #pragma unroll
        for (int j = 0; j < 4; j++) acc[i][j] = 0.f;

        if (t > 0) {
            auto wait_ck = [&](int ck){
                unsigned v;
                do { asm volatile("ld.acquire.gpu.global.u32 %0, [%1];"
                                  : "=r"(v) : "l"(&g_flag[gid][ck])); } while (v < tgt);
            };
            auto ldh = [&](int ck, int st){
                #pragma unroll
                for (int i = tid; i < 2048; i += 256) {
                    int r = i >> 4, q = i & 15;
                    CP16(sb + (HOFFf(st,r) + q*4)*4,
                         Hc + (size_t)(b0 + r)*Hsz + ck*128 + q*8);
                }
                CPCOMMIT();
            };

            wait_ck(0);
            ldh(0, 0);
            int st = 0, nst = 1;
            for (int ck = 0; ck < 4; ck++) {
                if (ck < 3) { wait_ck(ck+1); ldh(ck+1, nst); CPWAIT(1); }
                else        { CPWAIT(0); }
                __syncthreads();
                #pragma unroll
                for (int ks = 0; ks < 8; ks++) {
                    int kw = ks*8;
                    uint32_t ah[4], bh[4][4];
                    uint32_t aw = (uint32_t)(HOFFf(st, w*16 + laneA_r)) + kw + laneA_c;
                    LDSM4(ah, sb + aw*4);
                    #pragma unroll
                    for (int np = 0; np < 4; np++) {
                        uint32_t bw = (uint32_t)(WOFFf(ck, np*16 + laneB_r)) + kw + laneB_c;
                        LDSM4(bh[np], sb + bw*4);
                    }
                    #pragma unroll
                    for (int nt = 0; nt < 8; nt++)
                        mma16816(acc[nt], ah, &bh[nt>>1][(nt&1)*2]);
                }
                st = nst; nst = (nst + 1 == 3) ? 0 : nst + 1;
            }
        }

        // epilogue: gates + state update (c in registers, fast transcendentals)
        #pragma unroll
        for (int half = 0; half < 2; half++) {
            int b = b0 + w*16 + laneR + half*8;
            #pragma unroll
            for (int uh = 0; uh < 2; uh++) {
                float hn[2];
                #pragma unroll
                for (int du = 0; du < 2; du++) {
                    int q = half*2 + du;
                    float gi = acc[0*2+uh][q] + xv[half][uh*8+du*4+0];
                    float gf = acc[1*2+uh][q] + xv[half][uh*8+du*4+1];
                    float gg = acc[2*2+uh][q] + xv[half][uh*8+du*4+2];
                    float go = acc[3*2+uh][q] + xv[half][uh*8+du*4+3];
                    float is = fsig(gi);
                    float fs = fsig(gf);
                    float os = fsig(go);
                    float gt = ftanh(gg);
                    float cn = fs*creg[half][uh][du] + is*gt;
                    creg[half][uh][du] = cn;
                    hn[du] = os*ftanh(cn);
                }
                int u2 = u0 + laneC*2 + uh*8;
                __half2 hp;
                hp.x = __float2half_rn(hn[0]);
                hp.y = __float2half_rn(hn[1]);
                *(__half2*)(Nx + (size_t)b*Hsz + u2) = hp;
                *(__half2*)(seq + ((size_t)b*Tsz + t)*Hsz + u2) = hp;
            }
        }

        // publish (release-atomic; bar.sync + release forms the causality chain)
        if (t < Tsz - 1) {
            __syncthreads();
            if (tid == 0)
                asm volatile("red.release.gpu.global.add.u32 [%0], %1;"
                             :: "l"(&g_flag[gid][myck]), "r"(1u) : "memory");
        }
    }
}

// ---------------- merged fp32->fp16 conversion (Wih | Whh | decW | emb) ----------------
#define N4_W   524288
#define N4_D   65536
#define N4_E   65664
#define N4_ALL (N4_W + N4_W + N4_D + N4_E)
__global__ void conv_all(const float* __restrict__ Wih, const float* __restrict__ Whh,
                         const float* __restrict__ decW, const float* __restrict__ emb,
                         __half* __restrict__ oW, __half* __restrict__ oH,
                         __half* __restrict__ oD, __half* __restrict__ oE)
{
    int i = blockIdx.x*256 + threadIdx.x;
    if (i >= N4_ALL) return;
    const float* s; __half* d; int j;
    if (i < N4_W)                 { s = Wih;  d = oW; j = i; }
    else if (i < 2*N4_W)          { s = Whh;  d = oH; j = i - N4_W; }
    else if (i < 2*N4_W + N4_D)   { s = decW; d = oD; j = i - 2*N4_W; }
    else                          { s = emb;  d = oE; j = i - 2*N4_W - N4_D; }
    float4 v = ((const float4*)s)[j];
    __half2 a, b;
    a.x = __float2half_rn(v.x); a.y = __float2half_rn(v.y);
    b.x = __float2half_rn(v.z); b.y = __float2half_rn(v.w);
    ((__half2*)d)[j*2]   = a;
    ((__half2*)d)[j*2+1] = b;
}

// wy[u*4+g] = Wih0[n]·yW ; cb[u*4+g] = Wih0[n]·yb + bih0[n] + bhh0[n],  n = g*512+u
__global__ void prep_y(const float* __restrict__ Wih, const float* __restrict__ yW,
                       const float* __restrict__ yb, const float* __restrict__ bih,
                       const float* __restrict__ bhh,
                       float* __restrict__ wyv, float* __restrict__ cbv)
{
    int n = blockIdx.x*8 + (threadIdx.x >> 5);
    int lane = threadIdx.x & 31;
    const float* wr = Wih + (size_t)n*Hsz;
    float s1 = 0.f, s2 = 0.f;
    for (int k = lane; k < Hsz; k += 32) { float wv = wr[k]; s1 += wv*yW[k]; s2 += wv*yb[k]; }
    #pragma unroll
    for (int o = 16; o; o >>= 1) {
        s1 += __shfl_down_sync(0xFFFFFFFFu, s1, o);
        s2 += __shfl_down_sync(0xFFFFFFFFu, s2, o);
    }
    if (lane == 0) {
        int g = n >> 9, u = n & 511;
        wyv[u*4+g] = s1;
        cbv[u*4+g] = s2 + bih[n] + bhh[n];
    }
}

// ---------------- launch ----------------
extern "C" void kernel_launch(void* const* d_in, const int* in_sizes, int n_in,
                              void* d_out, int out_size)
{
    const int*   x    = (const int*)  d_in[0];
    const float* y    = (const float*)d_in[1];
    const float* emb  = (const float*)d_in[2];
    const float* yW   = (const float*)d_in[3];
    const float* yb   = (const float*)d_in[4];
    const float* Wih  = (const float*)d_in[5];
    const float* Whh  = (const float*)d_in[6];
    const float* bih  = (const float*)d_in[7];
    const float* bhh  = (const float*)d_in[8];
    const float* decW = (const float*)d_in[9];
    const float* decb = (const float*)d_in[10];
    float* out = (float*)d_out;

    __half *seq, *Wih_c, *Whh_c, *dW_c, *h0, *h1, *xgT, *embp, *Ep;
    float *wyv, *cbv;
    cudaGetSymbolAddress((void**)&seq,   g_seq);
    cudaGetSymbolAddress((void**)&xgT,   g_xgT);
    cudaGetSymbolAddress((void**)&h0,    g_h0);
    cudaGetSymbolAddress((void**)&h1,    g_h1);
    cudaGetSymbolAddress((void**)&Wih_c, g_Wih);
    cudaGetSymbolAddress((void**)&Whh_c, g_Whh);
    cudaGetSymbolAddress((void**)&dW_c,  g_dW);
    cudaGetSymbolAddress((void**)&embp,  g_embp);
    cudaGetSymbolAddress((void**)&Ep,    g_Ep);
    cudaGetSymbolAddress((void**)&wyv,   g_wyv);
    cudaGetSymbolAddress((void**)&cbv,   g_cbv);

    cudaFuncSetAttribute(gemm_mma, cudaFuncAttributeMaxDynamicSharedMemorySize, SMEMB);
    cudaFuncSetAttribute(lstm_persist, cudaFuncAttributeMaxDynamicSharedMemorySize, PS_SMEM);

    conv_all<<<(N4_ALL + 255)/256, 256>>>(Wih, Whh, decW, emb, Wih_c, Whh_c, dW_c, embp);
    prep_y<<<G4/8, 256>>>(Wih, yW, yb, bih, bhh, wyv, cbv);

    // E' = Wih0 · embp^T -> [tok][u][g] fp16
    gemm_mma<<<dim3(16, TOKP/128), 256, SMEMB>>>(
        Wih_c, embp, nullptr, nullptr, nullptr, Ep, TOKP, 0, 1, 2);

    // ---- layer 0: recurrence with E' gather (no xg GEMM) ----
    reset_flags<<<1, 32>>>();
    lstm_persist<<<dim3(Hsz/16, Bsz/128), 256, PS_SMEM>>>(
        0, xgT, Ep, wyv, cbv, x, y, Whh_c, h0, h1, seq);

    // ---- layer 1: xg GEMM + recurrence ----
    gemm_mma<<<dim3(16, NBT/128), 256, SMEMB>>>(
        Wih_c + (size_t)G4*Hsz, seq, bih + G4, bhh + G4, nullptr, xgT, NBT, 1, 1, 1);

    reset_flags<<<1, 32>>>();
    lstm_persist<<<dim3(Hsz/16, Bsz/128), 256, PS_SMEM>>>(
        1, xgT, Ep, wyv, cbv, x, y, Whh_c + (size_t)G4*Hsz, h0, h1, seq);

    // ---- decoder ----
    gemm_mma<<<dim3(Vsz/128, NBT/128), 256, SMEMB>>>(
        seq, dW_c, nullptr, nullptr, decb, out, Vsz, 0, 0, 0);
}